// round 1
// baseline (speedup 1.0000x reference)
#include <cuda_runtime.h>
#include <cuda_bf16.h>
#include <math.h>

// Problem constants
#define BATCH 2
#define T     2048
#define D     1024
#define NH    16
#define HD    64
#define ROWS  (BATCH * T)        // 4096
#define BHCNT (BATCH * NH)       // 32

// ---------------- scratch (device globals; no allocation allowed) -------------
__device__ float g_h   [(size_t)ROWS * D];            // 16 MB  (ln1 out / reused)
__device__ float g_qkv [(size_t)ROWS * 3 * D];        // 48 MB
__device__ float g_sc  [(size_t)BHCNT * T * T];       // 512 MB (scores -> weights in place)
__device__ float g_attn[(size_t)ROWS * D];            // 16 MB
__device__ float g_x1  [(size_t)ROWS * D];            // 16 MB
__device__ float g_h2  [(size_t)ROWS * D];            // 16 MB
__device__ float g_ffn [(size_t)ROWS * 4 * D];        // 64 MB

// ---------------- reductions ----------------
__device__ __forceinline__ float block_sum256(float v, float* red) {
    int t = threadIdx.x;
    #pragma unroll
    for (int o = 16; o > 0; o >>= 1) v += __shfl_xor_sync(0xffffffffu, v, o);
    if ((t & 31) == 0) red[t >> 5] = v;
    __syncthreads();
    float r;
    if (t < 32) {
        float s = (t < 8) ? red[t] : 0.0f;
        #pragma unroll
        for (int o = 4; o > 0; o >>= 1) s += __shfl_xor_sync(0xffffffffu, s, o);
        if (t == 0) red[0] = s;
    }
    __syncthreads();
    r = red[0];
    __syncthreads();
    return r;
}

__device__ __forceinline__ float block_max256(float v, float* red) {
    int t = threadIdx.x;
    #pragma unroll
    for (int o = 16; o > 0; o >>= 1) v = fmaxf(v, __shfl_xor_sync(0xffffffffu, v, o));
    if ((t & 31) == 0) red[t >> 5] = v;
    __syncthreads();
    float r;
    if (t < 32) {
        float s = (t < 8) ? red[t] : -INFINITY;
        #pragma unroll
        for (int o = 4; o > 0; o >>= 1) s = fmaxf(s, __shfl_xor_sync(0xffffffffu, s, o));
        if (t == 0) red[0] = s;
    }
    __syncthreads();
    r = red[0];
    __syncthreads();
    return r;
}

// ---------------- LayerNorm: one block per row of 1024 ----------------
__global__ __launch_bounds__(256) void ln_kernel(
    const float* __restrict__ x, const float* __restrict__ g,
    const float* __restrict__ b, float* __restrict__ out)
{
    __shared__ float red[32];
    int r = blockIdx.x;
    int t = threadIdx.x;
    const float* xr = x + (size_t)r * D;
    float4 v = *(const float4*)(xr + t * 4);
    float s = v.x + v.y + v.z + v.w;
    float mu = block_sum256(s, red) * (1.0f / D);
    float dx = v.x - mu, dy = v.y - mu, dz = v.z - mu, dw = v.w - mu;
    float ss = dx * dx + dy * dy + dz * dz + dw * dw;
    float var = block_sum256(ss, red) * (1.0f / D);
    float inv = rsqrtf(var + 1e-5f);
    float4 gv = *(const float4*)(g + t * 4);
    float4 bv = *(const float4*)(b + t * 4);
    float4 o;
    o.x = dx * inv * gv.x + bv.x;
    o.y = dy * inv * gv.y + bv.y;
    o.z = dz * inv * gv.z + bv.z;
    o.w = dw * inv * gv.w + bv.w;
    *(float4*)(out + (size_t)r * D + t * 4) = o;
}

// ---------------- Generic tiled GEMM: C = A[M,K] @ B[K,N] + bias, opt GELU / residual
template<bool GELU, bool RES>
__global__ __launch_bounds__(256) void gemm_kernel(
    const float* __restrict__ A, const float* __restrict__ B,
    const float* __restrict__ bias, const float* __restrict__ res,
    float* __restrict__ C, int M, int N, int K)
{
    const int BK = 16;
    __shared__ float As[BK][64];
    __shared__ float Bs[BK][64];
    int m0 = blockIdx.y * 64, n0 = blockIdx.x * 64;
    int t = threadIdx.x;
    int tx = t & 15, ty = t >> 4;
    int ar = t >> 2, ac4 = (t & 3) << 2;     // A: 64 rows x 4 float4
    int br = t >> 4, bc4 = (t & 15) << 2;    // B: 16 rows x 16 float4
    float acc[4][4] = {};
    for (int k0 = 0; k0 < K; k0 += BK) {
        float4 av = *(const float4*)(A + (size_t)(m0 + ar) * K + k0 + ac4);
        As[ac4 + 0][ar] = av.x; As[ac4 + 1][ar] = av.y;
        As[ac4 + 2][ar] = av.z; As[ac4 + 3][ar] = av.w;
        *(float4*)&Bs[br][bc4] = *(const float4*)(B + (size_t)(k0 + br) * N + n0 + bc4);
        __syncthreads();
        #pragma unroll
        for (int kk = 0; kk < BK; kk++) {
            float a[4], bb[4];
            #pragma unroll
            for (int i = 0; i < 4; i++) a[i] = As[kk][ty * 4 + i];
            #pragma unroll
            for (int j = 0; j < 4; j++) bb[j] = Bs[kk][tx * 4 + j];
            #pragma unroll
            for (int i = 0; i < 4; i++)
                #pragma unroll
                for (int j = 0; j < 4; j++) acc[i][j] += a[i] * bb[j];
        }
        __syncthreads();
    }
    #pragma unroll
    for (int i = 0; i < 4; i++) {
        int m = m0 + ty * 4 + i;
        int n = n0 + tx * 4;
        float4 o;
        float* po = &o.x;
        #pragma unroll
        for (int j = 0; j < 4; j++) {
            float v = acc[i][j] + bias[n + j];
            if (GELU) v = v * normcdff(v);
            if (RES)  v += res[(size_t)m * N + n + j];
            po[j] = v;
        }
        *(float4*)(C + (size_t)m * N + n) = o;
    }
}

// ---------------- attention scores: S[bh,q,k] = (Q . K)/8, causal tiles only
__global__ __launch_bounds__(256) void scores_kernel(
    const float* __restrict__ qkv, float* __restrict__ S)
{
    int kt = blockIdx.x, qt = blockIdx.y, bh = blockIdx.z;
    if (kt > qt) return;   // tile entirely above diagonal
    int b = bh >> 4, h = bh & 15;
    int q0 = qt * 64, k0 = kt * 64;
    __shared__ float Qs[64][64];   // [d][row]
    __shared__ float Ks[64][64];   // [d][row]
    int t = threadIdx.x;
    for (int i = t; i < 1024; i += 256) {
        int row = i >> 4;
        int c4  = (i & 15) << 2;
        const float* qp = qkv + (size_t)(b * T + q0 + row) * (3 * D) + h * HD + c4;
        float4 v = *(const float4*)qp;
        Qs[c4 + 0][row] = v.x; Qs[c4 + 1][row] = v.y;
        Qs[c4 + 2][row] = v.z; Qs[c4 + 3][row] = v.w;
        const float* kp = qkv + (size_t)(b * T + k0 + row) * (3 * D) + D + h * HD + c4;
        float4 w = *(const float4*)kp;
        Ks[c4 + 0][row] = w.x; Ks[c4 + 1][row] = w.y;
        Ks[c4 + 2][row] = w.z; Ks[c4 + 3][row] = w.w;
    }
    __syncthreads();
    int tx = t & 15, ty = t >> 4;
    float acc[4][4] = {};
    #pragma unroll 8
    for (int d = 0; d < 64; d++) {
        float a[4], bb[4];
        #pragma unroll
        for (int i = 0; i < 4; i++) a[i] = Qs[d][ty * 4 + i];
        #pragma unroll
        for (int j = 0; j < 4; j++) bb[j] = Ks[d][tx * 4 + j];
        #pragma unroll
        for (int i = 0; i < 4; i++)
            #pragma unroll
            for (int j = 0; j < 4; j++) acc[i][j] += a[i] * bb[j];
    }
    #pragma unroll
    for (int i = 0; i < 4; i++) {
        int q = q0 + ty * 4 + i;
        int k = k0 + tx * 4;
        float4 o;
        float* po = &o.x;
        #pragma unroll
        for (int j = 0; j < 4; j++) {
            float v = acc[i][j] * 0.125f;
            if (k + j > q) v = -INFINITY;
            po[j] = v;
        }
        *(float4*)(S + ((size_t)bh * T + q) * T + k) = o;
    }
}

// ---------------- causal softmax in place over S rows ----------------
__global__ __launch_bounds__(256) void softmax_kernel(float* __restrict__ S)
{
    __shared__ float buf[T];
    __shared__ float red[32];
    int r = blockIdx.x;          // bh*T + q
    int q = r & (T - 1);
    int n = q + 1;
    float* row = S + (size_t)r * T;
    int t = threadIdx.x;
    float mx = -INFINITY;
    for (int i = t; i < n; i += 256) { float v = row[i]; buf[i] = v; mx = fmaxf(mx, v); }
    mx = block_max256(mx, red);
    float sum = 0.0f;
    for (int i = t; i < n; i += 256) { float e = __expf(buf[i] - mx); buf[i] = e; sum += e; }
    sum = block_sum256(sum, red);
    float inv = 1.0f / sum;
    for (int i = t; i < T; i += 256) row[i] = (i < n) ? buf[i] * inv : 0.0f;
}

// ---------------- PV: O[b,q,h*64+d] = sum_k W[bh,q,k] * V[b,k,h,d] ----------------
__global__ __launch_bounds__(256) void pv_kernel(
    const float* __restrict__ W, const float* __restrict__ qkv, float* __restrict__ O)
{
    int qt = blockIdx.x, bh = blockIdx.z;
    int b = bh >> 4, h = bh & 15;
    int q0 = qt * 64;
    __shared__ float Ws[32][64];   // [k][q]
    __shared__ float Vs[32][64];   // [k][d]
    int t = threadIdx.x, tx = t & 15, ty = t >> 4;
    float acc[4][4] = {};
    const float* Wbase = W + (size_t)bh * T * T;
    int kmax = q0 + 64;            // causal: weights zero beyond q, tiles beyond q0+63 unneeded
    for (int k0 = 0; k0 < kmax; k0 += 32) {
        for (int i = t; i < 512; i += 256) {
            int qrow = i >> 3;  int c4 = (i & 7) << 2;
            float4 v = *(const float4*)(Wbase + (size_t)(q0 + qrow) * T + k0 + c4);
            Ws[c4 + 0][qrow] = v.x; Ws[c4 + 1][qrow] = v.y;
            Ws[c4 + 2][qrow] = v.z; Ws[c4 + 3][qrow] = v.w;
            int krow = i >> 4;  int d4 = (i & 15) << 2;
            float4 w = *(const float4*)(qkv + (size_t)(b * T + k0 + krow) * (3 * D) + 2 * D + h * HD + d4);
            *(float4*)&Vs[krow][d4] = w;
        }
        __syncthreads();
        #pragma unroll 8
        for (int kk = 0; kk < 32; kk++) {
            float a[4], bb[4];
            #pragma unroll
            for (int i = 0; i < 4; i++) a[i] = Ws[kk][ty * 4 + i];
            #pragma unroll
            for (int j = 0; j < 4; j++) bb[j] = Vs[kk][tx * 4 + j];
            #pragma unroll
            for (int i = 0; i < 4; i++)
                #pragma unroll
                for (int j = 0; j < 4; j++) acc[i][j] += a[i] * bb[j];
        }
        __syncthreads();
    }
    #pragma unroll
    for (int i = 0; i < 4; i++) {
        int q = q0 + ty * 4 + i;
        float4 o = make_float4(acc[i][0], acc[i][1], acc[i][2], acc[i][3]);
        *(float4*)(O + (size_t)(b * T + q) * D + h * HD + tx * 4) = o;
    }
}

// ---------------- launch ----------------
static float* sym_addr(const void* sym) {
    void* p = nullptr;
    cudaGetSymbolAddress(&p, sym);
    return (float*)p;
}

extern "C" void kernel_launch(void* const* d_in, const int* in_sizes, int n_in,
                              void* d_out, int out_size)
{
    const float* x     = (const float*)d_in[0];
    const float* w_qkv = (const float*)d_in[1];
    const float* b_qkv = (const float*)d_in[2];
    const float* w_fc  = (const float*)d_in[3];
    const float* b_fc  = (const float*)d_in[4];
    const float* ln1_g = (const float*)d_in[5];
    const float* ln1_b = (const float*)d_in[6];
    const float* ln2_g = (const float*)d_in[7];
    const float* ln2_b = (const float*)d_in[8];
    const float* w1    = (const float*)d_in[9];
    const float* b1    = (const float*)d_in[10];
    const float* w2    = (const float*)d_in[11];
    const float* b2    = (const float*)d_in[12];
    float* out = (float*)d_out;

    float* p_h    = sym_addr(g_h);
    float* p_qkv  = sym_addr(g_qkv);
    float* p_sc   = sym_addr(g_sc);
    float* p_attn = sym_addr(g_attn);
    float* p_x1   = sym_addr(g_x1);
    float* p_h2   = sym_addr(g_h2);
    float* p_ffn  = sym_addr(g_ffn);

    // 1. h = LN1(x)
    ln_kernel<<<ROWS, 256>>>(x, ln1_g, ln1_b, p_h);
    // 2. qkv = h @ w_qkv + b_qkv    [4096 x 3072]
    gemm_kernel<false, false><<<dim3(3 * D / 64, ROWS / 64), 256>>>(
        p_h, w_qkv, b_qkv, nullptr, p_qkv, ROWS, 3 * D, D);
    // 3. scores (causal tiles)
    scores_kernel<<<dim3(T / 64, T / 64, BHCNT), 256>>>(p_qkv, p_sc);
    // 4. softmax in place
    softmax_kernel<<<BHCNT * T, 256>>>(p_sc);
    // 5. attn_out = W @ V
    pv_kernel<<<dim3(T / 64, 1, BHCNT), 256>>>(p_sc, p_qkv, p_attn);
    // 6. x1 = x + attn_out @ w_fc + b_fc
    gemm_kernel<false, true><<<dim3(D / 64, ROWS / 64), 256>>>(
        p_attn, w_fc, b_fc, x, p_x1, ROWS, D, D);
    // 7. h2 = LN2(x1)
    ln_kernel<<<ROWS, 256>>>(p_x1, ln2_g, ln2_b, p_h2);
    // 8. ffn = gelu(h2 @ w1 + b1)   [4096 x 4096]
    gemm_kernel<true, false><<<dim3(4 * D / 64, ROWS / 64), 256>>>(
        p_h2, w1, b1, nullptr, p_ffn, ROWS, 4 * D, D);
    // 9. out = x1 + ffn @ w2 + b2
    gemm_kernel<false, true><<<dim3(D / 64, ROWS / 64), 256>>>(
        p_ffn, w2, b2, p_x1, out, ROWS, D, 4 * D);
}

// round 3
// speedup vs baseline: 2.1931x; 2.1931x over previous
#include <cuda_runtime.h>
#include <cuda_bf16.h>
#include <math.h>
#include <stdint.h>

// Problem constants
#define BATCH 2
#define T     2048
#define D     1024
#define NH    16
#define HD    64
#define ROWS  (BATCH * T)        // 4096
#define BHCNT (BATCH * NH)       // 32

// ---------------- scratch (device globals; no allocation allowed) -------------
__device__ float g_h    [(size_t)ROWS * D];
__device__ float g_qkv  [(size_t)ROWS * 3 * D];
__device__ float g_sc   [(size_t)BHCNT * T * T];       // 512 MB
__device__ float g_attn [(size_t)ROWS * D];
__device__ float g_x1   [(size_t)ROWS * D];
__device__ float g_h2   [(size_t)ROWS * D];
__device__ float g_ffn  [(size_t)ROWS * 4 * D];
__device__ float g_wqkvT[(size_t)3 * D * D];
__device__ float g_wfcT [(size_t)D * D];
__device__ float g_w1T  [(size_t)4 * D * D];
__device__ float g_w2T  [(size_t)4 * D * D];

// ======================= mma.sync tf32 GEMM =======================
// C[M,N] = A[M,K] @ Bt[N,K]^T (+bias, opt GELU, opt residual)
// CTA tile 128x128, BK=32, 8 warps in 2x4 (warp tile 64x32), double-buffered cp.async.
#define RSTRIDE 36                      // smem row stride in floats (bank-conflict-free frags)
#define TILE_F  (128 * RSTRIDE)        // floats per tile buffer
#define TILE_B  (TILE_F * 4)           // 18432 bytes
#define BUF_B   (2 * TILE_B)           // A+B per buffer stage = 36864
#define GEMM_SMEM (2 * BUF_B)          // 73728 bytes

__device__ __forceinline__ uint32_t smem_u32(const void* p) {
    uint32_t a;
    asm("{ .reg .u64 t; cvta.to.shared.u64 t, %1; cvt.u32.u64 %0, t; }" : "=r"(a) : "l"(p));
    return a;
}
__device__ __forceinline__ void cp_async16(uint32_t s, const void* g) {
    asm volatile("cp.async.ca.shared.global [%0], [%1], 16;" :: "r"(s), "l"(g));
}
__device__ __forceinline__ void cp_commit() {
    asm volatile("cp.async.commit_group;" ::: "memory");
}
template<int N>
__device__ __forceinline__ void cp_wait() {
    asm volatile("cp.async.wait_group %0;" :: "n"(N) : "memory");
}
__device__ __forceinline__ uint32_t rna_tf32(float v) {
    return __float_as_uint(v) + 0x1000u;   // round-to-nearest-away into tf32 field
}
__device__ __forceinline__ void mma_tf32(float* c, const uint32_t* a, const uint32_t* b) {
    asm volatile(
        "mma.sync.aligned.m16n8k8.row.col.f32.tf32.tf32.f32 "
        "{%0,%1,%2,%3}, {%4,%5,%6,%7}, {%8,%9}, {%0,%1,%2,%3};"
        : "+f"(c[0]), "+f"(c[1]), "+f"(c[2]), "+f"(c[3])
        : "r"(a[0]), "r"(a[1]), "r"(a[2]), "r"(a[3]), "r"(b[0]), "r"(b[1]));
}

template<bool GELU, bool RES>
__global__ __launch_bounds__(256) void gemm_mma(
    const float* __restrict__ A, const float* __restrict__ Bt,
    const float* __restrict__ bias, const float* __restrict__ res,
    float* __restrict__ C, int M, int N, int K)
{
    extern __shared__ char smem[];
    const uint32_t sb = smem_u32(smem);
    int t = threadIdx.x;
    int wid = t >> 5, lane = t & 31;
    int wm = wid >> 2, wn = wid & 3;          // warp grid 2x4
    int group = lane >> 2, qd = lane & 3;
    int m0 = blockIdx.y * 128, n0 = blockIdx.x * 128;

    const float* Ap = A + (size_t)m0 * K;
    const float* Bp = Bt + (size_t)n0 * K;

    // cp.async loader: 1024 x 16B segs per tile; thread does 4 A-segs + 4 B-segs
    auto load_chunk = [&](int c, int buf) {
        uint32_t sa = sb + buf * BUF_B;
        uint32_t sbB = sa + TILE_B;
        const float* Ag = Ap + c * 32;
        const float* Bg = Bp + c * 32;
        #pragma unroll
        for (int i = 0; i < 4; i++) {
            int idx = t + i * 256;
            int row = idx >> 3, seg = idx & 7;
            cp_async16(sa  + row * (RSTRIDE * 4) + seg * 16, Ag + (size_t)row * K + seg * 4);
            cp_async16(sbB + row * (RSTRIDE * 4) + seg * 16, Bg + (size_t)row * K + seg * 4);
        }
        cp_commit();
    };

    float acc[4][4][4] = {};
    int nch = K / 32;

    load_chunk(0, 0);
    for (int c = 0; c < nch; c++) {
        if (c + 1 < nch) { load_chunk(c + 1, (c + 1) & 1); cp_wait<1>(); }
        else             { cp_wait<0>(); }
        __syncthreads();

        const float* As = (const float*)(smem + (c & 1) * BUF_B);
        const float* Bs = As + TILE_F;
        #pragma unroll
        for (int s = 0; s < 4; s++) {
            uint32_t af[4][4], bf[4][2];
            #pragma unroll
            for (int mt = 0; mt < 4; mt++) {
                int r = wm * 64 + mt * 16 + group;
                const float* ap = As + r * RSTRIDE + s * 8 + qd;
                af[mt][0] = rna_tf32(ap[0]);
                af[mt][2] = rna_tf32(ap[4]);
                af[mt][1] = rna_tf32(ap[8 * RSTRIDE]);
                af[mt][3] = rna_tf32(ap[8 * RSTRIDE + 4]);
            }
            #pragma unroll
            for (int nt = 0; nt < 4; nt++) {
                int n = wn * 32 + nt * 8 + group;
                const float* bp = Bs + n * RSTRIDE + s * 8 + qd;
                bf[nt][0] = rna_tf32(bp[0]);
                bf[nt][1] = rna_tf32(bp[4]);
            }
            #pragma unroll
            for (int mt = 0; mt < 4; mt++)
                #pragma unroll
                for (int nt = 0; nt < 4; nt++)
                    mma_tf32(acc[mt][nt], af[mt], bf[nt]);
        }
        __syncthreads();
    }

    // epilogue: direct STG (float2 per c-pair)
    #pragma unroll
    for (int nt = 0; nt < 4; nt++) {
        int n = n0 + wn * 32 + nt * 8 + qd * 2;
        float2 bv = *(const float2*)(bias + n);
        #pragma unroll
        for (int mt = 0; mt < 4; mt++) {
            int m = m0 + wm * 64 + mt * 16 + group;
            float* c4 = acc[mt][nt];
            float2 v0 = make_float2(c4[0] + bv.x, c4[1] + bv.y);
            float2 v1 = make_float2(c4[2] + bv.x, c4[3] + bv.y);
            if (GELU) {
                v0.x *= normcdff(v0.x); v0.y *= normcdff(v0.y);
                v1.x *= normcdff(v1.x); v1.y *= normcdff(v1.y);
            }
            if (RES) {
                float2 r0 = *(const float2*)(res + (size_t)m * N + n);
                float2 r1 = *(const float2*)(res + (size_t)(m + 8) * N + n);
                v0.x += r0.x; v0.y += r0.y; v1.x += r1.x; v1.y += r1.y;
            }
            *(float2*)(C + (size_t)m * N + n) = v0;
            *(float2*)(C + (size_t)(m + 8) * N + n) = v1;
        }
    }
}

// ======================= transpose (weights: [K,N] -> [N,K]) =======================
__global__ __launch_bounds__(256) void transpose_kernel(
    const float* __restrict__ in, float* __restrict__ out, int K, int N)
{
    __shared__ float tile[32][33];
    int k0 = blockIdx.y * 32, n0 = blockIdx.x * 32;
    int tx = threadIdx.x, ty = threadIdx.y;   // 32 x 8
    #pragma unroll
    for (int i = 0; i < 32; i += 8)
        tile[ty + i][tx] = in[(size_t)(k0 + ty + i) * N + n0 + tx];
    __syncthreads();
    #pragma unroll
    for (int i = 0; i < 32; i += 8)
        out[(size_t)(n0 + ty + i) * K + k0 + tx] = tile[tx][ty + i];
}

// ======================= reductions / LN / attention (SIMT fp32) =======================
__device__ __forceinline__ float block_sum256(float v, float* red) {
    int t = threadIdx.x;
    #pragma unroll
    for (int o = 16; o > 0; o >>= 1) v += __shfl_xor_sync(0xffffffffu, v, o);
    if ((t & 31) == 0) red[t >> 5] = v;
    __syncthreads();
    if (t < 32) {
        float s = (t < 8) ? red[t] : 0.0f;
        #pragma unroll
        for (int o = 4; o > 0; o >>= 1) s += __shfl_xor_sync(0xffffffffu, s, o);
        if (t == 0) red[0] = s;
    }
    __syncthreads();
    float r = red[0];
    __syncthreads();
    return r;
}
__device__ __forceinline__ float block_max256(float v, float* red) {
    int t = threadIdx.x;
    #pragma unroll
    for (int o = 16; o > 0; o >>= 1) v = fmaxf(v, __shfl_xor_sync(0xffffffffu, v, o));
    if ((t & 31) == 0) red[t >> 5] = v;
    __syncthreads();
    if (t < 32) {
        float s = (t < 8) ? red[t] : -INFINITY;
        #pragma unroll
        for (int o = 4; o > 0; o >>= 1) s = fmaxf(s, __shfl_xor_sync(0xffffffffu, s, o));
        if (t == 0) red[0] = s;
    }
    __syncthreads();
    float r = red[0];
    __syncthreads();
    return r;
}

__global__ __launch_bounds__(256) void ln_kernel(
    const float* __restrict__ x, const float* __restrict__ g,
    const float* __restrict__ b, float* __restrict__ out)
{
    __shared__ float red[32];
    int r = blockIdx.x, t = threadIdx.x;
    const float* xr = x + (size_t)r * D;
    float4 v = *(const float4*)(xr + t * 4);
    float mu = block_sum256(v.x + v.y + v.z + v.w, red) * (1.0f / D);
    float dx = v.x - mu, dy = v.y - mu, dz = v.z - mu, dw = v.w - mu;
    float var = block_sum256(dx * dx + dy * dy + dz * dz + dw * dw, red) * (1.0f / D);
    float inv = rsqrtf(var + 1e-5f);
    float4 gv = *(const float4*)(g + t * 4);
    float4 bv = *(const float4*)(b + t * 4);
    float4 o;
    o.x = dx * inv * gv.x + bv.x; o.y = dy * inv * gv.y + bv.y;
    o.z = dz * inv * gv.z + bv.z; o.w = dw * inv * gv.w + bv.w;
    *(float4*)(out + (size_t)r * D + t * 4) = o;
}

__global__ __launch_bounds__(256) void scores_kernel(
    const float* __restrict__ qkv, float* __restrict__ S)
{
    int kt = blockIdx.x, qt = blockIdx.y, bh = blockIdx.z;
    if (kt > qt) return;
    int b = bh >> 4, h = bh & 15;
    int q0 = qt * 64, k0 = kt * 64;
    __shared__ float Qs[64][64];
    __shared__ float Ks[64][64];
    int t = threadIdx.x;
    for (int i = t; i < 1024; i += 256) {
        int row = i >> 4, c4 = (i & 15) << 2;
        float4 v = *(const float4*)(qkv + (size_t)(b * T + q0 + row) * (3 * D) + h * HD + c4);
        Qs[c4 + 0][row] = v.x; Qs[c4 + 1][row] = v.y; Qs[c4 + 2][row] = v.z; Qs[c4 + 3][row] = v.w;
        float4 w = *(const float4*)(qkv + (size_t)(b * T + k0 + row) * (3 * D) + D + h * HD + c4);
        Ks[c4 + 0][row] = w.x; Ks[c4 + 1][row] = w.y; Ks[c4 + 2][row] = w.z; Ks[c4 + 3][row] = w.w;
    }
    __syncthreads();
    int tx = t & 15, ty = t >> 4;
    float acc[4][4] = {};
    #pragma unroll 8
    for (int d = 0; d < 64; d++) {
        float a[4], bb[4];
        #pragma unroll
        for (int i = 0; i < 4; i++) a[i] = Qs[d][ty * 4 + i];
        #pragma unroll
        for (int j = 0; j < 4; j++) bb[j] = Ks[d][tx * 4 + j];
        #pragma unroll
        for (int i = 0; i < 4; i++)
            #pragma unroll
            for (int j = 0; j < 4; j++) acc[i][j] += a[i] * bb[j];
    }
    #pragma unroll
    for (int i = 0; i < 4; i++) {
        int q = q0 + ty * 4 + i, k = k0 + tx * 4;
        float4 o; float* po = &o.x;
        #pragma unroll
        for (int j = 0; j < 4; j++) {
            float v = acc[i][j] * 0.125f;
            if (k + j > q) v = -INFINITY;
            po[j] = v;
        }
        *(float4*)(S + ((size_t)bh * T + q) * T + k) = o;
    }
}

__global__ __launch_bounds__(256) void softmax_kernel(float* __restrict__ S)
{
    __shared__ float buf[T];
    __shared__ float red[32];
    int r = blockIdx.x;
    int q = r & (T - 1);
    int n = q + 1;
    float* row = S + (size_t)r * T;
    int t = threadIdx.x;
    float mx = -INFINITY;
    for (int i = t; i < n; i += 256) { float v = row[i]; buf[i] = v; mx = fmaxf(mx, v); }
    mx = block_max256(mx, red);
    float sum = 0.0f;
    for (int i = t; i < n; i += 256) { float e = __expf(buf[i] - mx); buf[i] = e; sum += e; }
    sum = block_sum256(sum, red);
    float inv = 1.0f / sum;
    for (int i = t; i < T; i += 256) row[i] = (i < n) ? buf[i] * inv : 0.0f;
}

__global__ __launch_bounds__(256) void pv_kernel(
    const float* __restrict__ W, const float* __restrict__ qkv, float* __restrict__ O)
{
    int qt = blockIdx.x, bh = blockIdx.z;
    int b = bh >> 4, h = bh & 15;
    int q0 = qt * 64;
    __shared__ float Ws[32][64];
    __shared__ float Vs[32][64];
    int t = threadIdx.x, tx = t & 15, ty = t >> 4;
    float acc[4][4] = {};
    const float* Wbase = W + (size_t)bh * T * T;
    int kmax = q0 + 64;
    for (int k0 = 0; k0 < kmax; k0 += 32) {
        for (int i = t; i < 512; i += 256) {
            int qrow = i >> 3; int c4 = (i & 7) << 2;
            float4 v = *(const float4*)(Wbase + (size_t)(q0 + qrow) * T + k0 + c4);
            Ws[c4 + 0][qrow] = v.x; Ws[c4 + 1][qrow] = v.y;
            Ws[c4 + 2][qrow] = v.z; Ws[c4 + 3][qrow] = v.w;
            int krow = i >> 4; int d4 = (i & 15) << 2;
            *(float4*)&Vs[krow][d4] =
                *(const float4*)(qkv + (size_t)(b * T + k0 + krow) * (3 * D) + 2 * D + h * HD + d4);
        }
        __syncthreads();
        #pragma unroll 8
        for (int kk = 0; kk < 32; kk++) {
            float a[4], bb[4];
            #pragma unroll
            for (int i = 0; i < 4; i++) a[i] = Ws[kk][ty * 4 + i];
            #pragma unroll
            for (int j = 0; j < 4; j++) bb[j] = Vs[kk][tx * 4 + j];
            #pragma unroll
            for (int i = 0; i < 4; i++)
                #pragma unroll
                for (int j = 0; j < 4; j++) acc[i][j] += a[i] * bb[j];
        }
        __syncthreads();
    }
    #pragma unroll
    for (int i = 0; i < 4; i++) {
        int q = q0 + ty * 4 + i;
        float4 o = make_float4(acc[i][0], acc[i][1], acc[i][2], acc[i][3]);
        *(float4*)(O + (size_t)(b * T + q) * D + h * HD + tx * 4) = o;
    }
}

// ======================= launch =======================
static float* sym_addr(const void* sym) {
    void* p = nullptr;
    cudaGetSymbolAddress(&p, sym);
    return (float*)p;
}

extern "C" void kernel_launch(void* const* d_in, const int* in_sizes, int n_in,
                              void* d_out, int out_size)
{
    const float* x     = (const float*)d_in[0];
    const float* w_qkv = (const float*)d_in[1];
    const float* b_qkv = (const float*)d_in[2];
    const float* w_fc  = (const float*)d_in[3];
    const float* b_fc  = (const float*)d_in[4];
    const float* ln1_g = (const float*)d_in[5];
    const float* ln1_b = (const float*)d_in[6];
    const float* ln2_g = (const float*)d_in[7];
    const float* ln2_b = (const float*)d_in[8];
    const float* w1    = (const float*)d_in[9];
    const float* b1    = (const float*)d_in[10];
    const float* w2    = (const float*)d_in[11];
    const float* b2    = (const float*)d_in[12];
    float* out = (float*)d_out;

    float* p_h     = sym_addr(g_h);
    float* p_qkv   = sym_addr(g_qkv);
    float* p_sc    = sym_addr(g_sc);
    float* p_attn  = sym_addr(g_attn);
    float* p_x1    = sym_addr(g_x1);
    float* p_h2    = sym_addr(g_h2);
    float* p_ffn   = sym_addr(g_ffn);
    float* p_wqkvT = sym_addr(g_wqkvT);
    float* p_wfcT  = sym_addr(g_wfcT);
    float* p_w1T   = sym_addr(g_w1T);
    float* p_w2T   = sym_addr(g_w2T);

    cudaFuncSetAttribute(gemm_mma<false, false>, cudaFuncAttributeMaxDynamicSharedMemorySize, GEMM_SMEM);
    cudaFuncSetAttribute(gemm_mma<false, true>,  cudaFuncAttributeMaxDynamicSharedMemorySize, GEMM_SMEM);
    cudaFuncSetAttribute(gemm_mma<true,  false>, cudaFuncAttributeMaxDynamicSharedMemorySize, GEMM_SMEM);

    // weight transposes: [K,N] -> [N,K]
    transpose_kernel<<<dim3(3 * D / 32, D / 32), dim3(32, 8)>>>(w_qkv, p_wqkvT, D, 3 * D);
    transpose_kernel<<<dim3(D / 32, D / 32),     dim3(32, 8)>>>(w_fc,  p_wfcT,  D, D);
    transpose_kernel<<<dim3(4 * D / 32, D / 32), dim3(32, 8)>>>(w1,    p_w1T,   D, 4 * D);
    transpose_kernel<<<dim3(D / 32, 4 * D / 32), dim3(32, 8)>>>(w2,    p_w2T,   4 * D, D);

    // 1. h = LN1(x)
    ln_kernel<<<ROWS, 256>>>(x, ln1_g, ln1_b, p_h);
    // 2. qkv = h @ w_qkv + b_qkv
    gemm_mma<false, false><<<dim3(3 * D / 128, ROWS / 128), 256, GEMM_SMEM>>>(
        p_h, p_wqkvT, b_qkv, nullptr, p_qkv, ROWS, 3 * D, D);
    // 3-5. attention
    scores_kernel<<<dim3(T / 64, T / 64, BHCNT), 256>>>(p_qkv, p_sc);
    softmax_kernel<<<BHCNT * T, 256>>>(p_sc);
    pv_kernel<<<dim3(T / 64, 1, BHCNT), 256>>>(p_sc, p_qkv, p_attn);
    // 6. x1 = x + attn @ w_fc + b_fc
    gemm_mma<false, true><<<dim3(D / 128, ROWS / 128), 256, GEMM_SMEM>>>(
        p_attn, p_wfcT, b_fc, x, p_x1, ROWS, D, D);
    // 7. h2 = LN2(x1)
    ln_kernel<<<ROWS, 256>>>(p_x1, ln2_g, ln2_b, p_h2);
    // 8. ffn = gelu(h2 @ w1 + b1)
    gemm_mma<true, false><<<dim3(4 * D / 128, ROWS / 128), 256, GEMM_SMEM>>>(
        p_h2, p_w1T, b1, nullptr, p_ffn, ROWS, 4 * D, D);
    // 9. out = x1 + ffn @ w2 + b2
    gemm_mma<false, true><<<dim3(D / 128, ROWS / 128), 256, GEMM_SMEM>>>(
        p_ffn, p_w2T, b2, p_x1, out, ROWS, D, 4 * D);
}

// round 4
// speedup vs baseline: 3.6916x; 1.6833x over previous
#include <cuda_runtime.h>
#include <cuda_bf16.h>
#include <math.h>
#include <stdint.h>

// Problem constants
#define BATCH 2
#define T     2048
#define D     1024
#define NH    16
#define HD    64
#define ROWS  (BATCH * T)        // 4096
#define BHCNT (BATCH * NH)       // 32

// ---------------- scratch (device globals; no allocation allowed) -------------
__device__ float g_h    [(size_t)ROWS * D];
__device__ float g_qkv  [(size_t)ROWS * 3 * D];
__device__ float g_attn [(size_t)ROWS * D];
__device__ float g_x1   [(size_t)ROWS * D];
__device__ float g_h2   [(size_t)ROWS * D];
__device__ float g_ffn  [(size_t)ROWS * 4 * D];
__device__ float g_wqkvT[(size_t)3 * D * D];
__device__ float g_wfcT [(size_t)D * D];
__device__ float g_w1T  [(size_t)4 * D * D];
__device__ float g_w2T  [(size_t)4 * D * D];

// ======================= common helpers =======================
__device__ __forceinline__ uint32_t smem_u32(const void* p) {
    uint32_t a;
    asm("{ .reg .u64 t; cvta.to.shared.u64 t, %1; cvt.u32.u64 %0, t; }" : "=r"(a) : "l"(p));
    return a;
}
__device__ __forceinline__ void cp_async16(uint32_t s, const void* g) {
    asm volatile("cp.async.ca.shared.global [%0], [%1], 16;" :: "r"(s), "l"(g));
}
__device__ __forceinline__ void cp_commit() {
    asm volatile("cp.async.commit_group;" ::: "memory");
}
template<int N>
__device__ __forceinline__ void cp_wait() {
    asm volatile("cp.async.wait_group %0;" :: "n"(N) : "memory");
}
__device__ __forceinline__ uint32_t rna_tf32(float v) {
    return __float_as_uint(v) + 0x1000u;   // round-to-nearest-away into tf32 field
}
__device__ __forceinline__ void mma_tf32(float* c, const uint32_t* a, const uint32_t* b) {
    asm volatile(
        "mma.sync.aligned.m16n8k8.row.col.f32.tf32.tf32.f32 "
        "{%0,%1,%2,%3}, {%4,%5,%6,%7}, {%8,%9}, {%0,%1,%2,%3};"
        : "+f"(c[0]), "+f"(c[1]), "+f"(c[2]), "+f"(c[3])
        : "r"(a[0]), "r"(a[1]), "r"(a[2]), "r"(a[3]), "r"(b[0]), "r"(b[1]));
}

// ======================= mma.sync tf32 GEMM =======================
#define RSTRIDE 36
#define TILE_F  (128 * RSTRIDE)
#define TILE_B  (TILE_F * 4)
#define BUF_B   (2 * TILE_B)
#define GEMM_SMEM (2 * BUF_B)

template<bool GELU, bool RES>
__global__ __launch_bounds__(256) void gemm_mma(
    const float* __restrict__ A, const float* __restrict__ Bt,
    const float* __restrict__ bias, const float* __restrict__ res,
    float* __restrict__ C, int M, int N, int K)
{
    extern __shared__ char smem[];
    const uint32_t sb = smem_u32(smem);
    int t = threadIdx.x;
    int wid = t >> 5, lane = t & 31;
    int wm = wid >> 2, wn = wid & 3;
    int group = lane >> 2, qd = lane & 3;
    int m0 = blockIdx.y * 128, n0 = blockIdx.x * 128;

    const float* Ap = A + (size_t)m0 * K;
    const float* Bp = Bt + (size_t)n0 * K;

    auto load_chunk = [&](int c, int buf) {
        uint32_t sa = sb + buf * BUF_B;
        uint32_t sbB = sa + TILE_B;
        const float* Ag = Ap + c * 32;
        const float* Bg = Bp + c * 32;
        #pragma unroll
        for (int i = 0; i < 4; i++) {
            int idx = t + i * 256;
            int row = idx >> 3, seg = idx & 7;
            cp_async16(sa  + row * (RSTRIDE * 4) + seg * 16, Ag + (size_t)row * K + seg * 4);
            cp_async16(sbB + row * (RSTRIDE * 4) + seg * 16, Bg + (size_t)row * K + seg * 4);
        }
        cp_commit();
    };

    float acc[4][4][4] = {};
    int nch = K / 32;

    load_chunk(0, 0);
    for (int c = 0; c < nch; c++) {
        if (c + 1 < nch) { load_chunk(c + 1, (c + 1) & 1); cp_wait<1>(); }
        else             { cp_wait<0>(); }
        __syncthreads();

        const float* As = (const float*)(smem + (c & 1) * BUF_B);
        const float* Bs = As + TILE_F;
        #pragma unroll
        for (int s = 0; s < 4; s++) {
            uint32_t af[4][4], bf[4][2];
            #pragma unroll
            for (int mt = 0; mt < 4; mt++) {
                int r = wm * 64 + mt * 16 + group;
                const float* ap = As + r * RSTRIDE + s * 8 + qd;
                af[mt][0] = rna_tf32(ap[0]);
                af[mt][2] = rna_tf32(ap[4]);
                af[mt][1] = rna_tf32(ap[8 * RSTRIDE]);
                af[mt][3] = rna_tf32(ap[8 * RSTRIDE + 4]);
            }
            #pragma unroll
            for (int nt = 0; nt < 4; nt++) {
                int n = wn * 32 + nt * 8 + group;
                const float* bp = Bs + n * RSTRIDE + s * 8 + qd;
                bf[nt][0] = rna_tf32(bp[0]);
                bf[nt][1] = rna_tf32(bp[4]);
            }
            #pragma unroll
            for (int mt = 0; mt < 4; mt++)
                #pragma unroll
                for (int nt = 0; nt < 4; nt++)
                    mma_tf32(acc[mt][nt], af[mt], bf[nt]);
        }
        __syncthreads();
    }

    #pragma unroll
    for (int nt = 0; nt < 4; nt++) {
        int n = n0 + wn * 32 + nt * 8 + qd * 2;
        float2 bv = *(const float2*)(bias + n);
        #pragma unroll
        for (int mt = 0; mt < 4; mt++) {
            int m = m0 + wm * 64 + mt * 16 + group;
            float* c4 = acc[mt][nt];
            float2 v0 = make_float2(c4[0] + bv.x, c4[1] + bv.y);
            float2 v1 = make_float2(c4[2] + bv.x, c4[3] + bv.y);
            if (GELU) {
                v0.x *= normcdff(v0.x); v0.y *= normcdff(v0.y);
                v1.x *= normcdff(v1.x); v1.y *= normcdff(v1.y);
            }
            if (RES) {
                float2 r0 = *(const float2*)(res + (size_t)m * N + n);
                float2 r1 = *(const float2*)(res + (size_t)(m + 8) * N + n);
                v0.x += r0.x; v0.y += r0.y; v1.x += r1.x; v1.y += r1.y;
            }
            *(float2*)(C + (size_t)m * N + n) = v0;
            *(float2*)(C + (size_t)(m + 8) * N + n) = v1;
        }
    }
}

// ======================= flash attention (tf32 mma) =======================
// grid (T/64, BHCNT), 128 threads (4 warps x 16 q-rows).
#define FA_KP 68   // row stride (floats) for K tiles and P staging
#define FA_VP 72   // row stride for V tiles
#define FA_SMEM_B ((3 * 64 * FA_KP + 2 * 64 * FA_VP) * 4)   // 89088 B

__global__ __launch_bounds__(128) void flash_kernel(
    const float* __restrict__ qkv, float* __restrict__ O)
{
    extern __shared__ float sm[];
    float* Ps = sm;                                   // 64 x FA_KP (also Q staging)
    const uint32_t sb = smem_u32(sm);
    const uint32_t kB[2] = { sb + 64u * FA_KP * 4, sb + 2u * 64 * FA_KP * 4 };
    const uint32_t vB[2] = { sb + 3u * 64 * FA_KP * 4,
                             sb + 3u * 64 * FA_KP * 4 + 64u * FA_VP * 4 };
    const float* Kp[2] = { sm + 64 * FA_KP, sm + 2 * 64 * FA_KP };
    const float* Vp[2] = { sm + 3 * 64 * FA_KP, sm + 3 * 64 * FA_KP + 64 * FA_VP };

    int qt = blockIdx.x, bh = blockIdx.y;
    int b = bh >> 4, h = bh & 15;
    int q0 = qt * 64;
    int t = threadIdx.x, w = t >> 5, lane = t & 31, gp = lane >> 2, qd = lane & 3;

    // stage Q tile into Ps, pull fragments into registers
    for (int i = t; i < 64 * 16; i += 128) {
        int row = i >> 4, sg = i & 15;
        *(float4*)(Ps + row * FA_KP + sg * 4) =
            *(const float4*)(qkv + (size_t)(b * T + q0 + row) * (3 * D) + h * HD + sg * 4);
    }
    __syncthreads();
    uint32_t qf[8][4];
    #pragma unroll
    for (int ks = 0; ks < 8; ks++) {
        const float* ap = Ps + (w * 16 + gp) * FA_KP + ks * 8 + qd;
        qf[ks][0] = rna_tf32(ap[0]);
        qf[ks][1] = rna_tf32(ap[8 * FA_KP]);
        qf[ks][2] = rna_tf32(ap[4]);
        qf[ks][3] = rna_tf32(ap[8 * FA_KP + 4]);
    }
    __syncthreads();

    auto load_kv = [&](int kt, int bf) {
        const float* kg = qkv + (size_t)(b * T + kt * 64) * (3 * D) + D + h * HD;
        #pragma unroll
        for (int i = 0; i < 8; i++) {
            int idx = t + i * 128;
            int row = idx >> 4, sg = idx & 15;
            const float* kr = kg + (size_t)row * (3 * D) + sg * 4;
            cp_async16(kB[bf] + row * (FA_KP * 4) + sg * 16, kr);
            cp_async16(vB[bf] + row * (FA_VP * 4) + sg * 16, kr + D);
        }
        cp_commit();
    };

    float m0 = -INFINITY, m1 = -INFINITY, l0 = 0.f, l1 = 0.f;
    float o[8][4] = {};

    load_kv(0, 0);
    for (int kt = 0; kt <= qt; kt++) {
        int bf = kt & 1;
        if (kt < qt) { load_kv(kt + 1, bf ^ 1); cp_wait<1>(); }
        else         { cp_wait<0>(); }
        __syncthreads();

        // S = Q @ K^T
        float s[8][4] = {};
        const float* Ksm = Kp[bf];
        #pragma unroll
        for (int ks = 0; ks < 8; ks++) {
            #pragma unroll
            for (int nt = 0; nt < 8; nt++) {
                uint32_t bfr[2];
                const float* bp = Ksm + (nt * 8 + gp) * FA_KP + ks * 8 + qd;
                bfr[0] = rna_tf32(bp[0]); bfr[1] = rna_tf32(bp[4]);
                mma_tf32(s[nt], qf[ks], bfr);
            }
        }
        // scale + causal mask (diagonal tile only)
        bool diag = (kt == qt);
        int r0l = w * 16 + gp;
        #pragma unroll
        for (int nt = 0; nt < 8; nt++) {
            int c = nt * 8 + 2 * qd;
            s[nt][0] *= 0.125f; s[nt][1] *= 0.125f;
            s[nt][2] *= 0.125f; s[nt][3] *= 0.125f;
            if (diag) {
                if (c     > r0l)     s[nt][0] = -INFINITY;
                if (c + 1 > r0l)     s[nt][1] = -INFINITY;
                if (c     > r0l + 8) s[nt][2] = -INFINITY;
                if (c + 1 > r0l + 8) s[nt][3] = -INFINITY;
            }
        }
        // online softmax
        float mx0 = -INFINITY, mx1 = -INFINITY;
        #pragma unroll
        for (int nt = 0; nt < 8; nt++) {
            mx0 = fmaxf(mx0, fmaxf(s[nt][0], s[nt][1]));
            mx1 = fmaxf(mx1, fmaxf(s[nt][2], s[nt][3]));
        }
        mx0 = fmaxf(mx0, __shfl_xor_sync(~0u, mx0, 1));
        mx0 = fmaxf(mx0, __shfl_xor_sync(~0u, mx0, 2));
        mx1 = fmaxf(mx1, __shfl_xor_sync(~0u, mx1, 1));
        mx1 = fmaxf(mx1, __shfl_xor_sync(~0u, mx1, 2));
        float mn0 = fmaxf(m0, mx0), mn1 = fmaxf(m1, mx1);
        float sc0 = __expf(m0 - mn0), sc1 = __expf(m1 - mn1);
        m0 = mn0; m1 = mn1;
        float ls0 = 0.f, ls1 = 0.f;
        float* Pw = Ps + (w * 16 + gp) * FA_KP + 2 * qd;
        #pragma unroll
        for (int nt = 0; nt < 8; nt++) {
            float p0 = __expf(s[nt][0] - mn0), p1 = __expf(s[nt][1] - mn0);
            float p2 = __expf(s[nt][2] - mn1), p3 = __expf(s[nt][3] - mn1);
            ls0 += p0 + p1; ls1 += p2 + p3;
            *(float2*)(Pw + nt * 8) = make_float2(p0, p1);
            *(float2*)(Pw + 8 * FA_KP + nt * 8) = make_float2(p2, p3);
        }
        ls0 += __shfl_xor_sync(~0u, ls0, 1); ls0 += __shfl_xor_sync(~0u, ls0, 2);
        ls1 += __shfl_xor_sync(~0u, ls1, 1); ls1 += __shfl_xor_sync(~0u, ls1, 2);
        l0 = l0 * sc0 + ls0; l1 = l1 * sc1 + ls1;
        #pragma unroll
        for (int nt = 0; nt < 8; nt++) {
            o[nt][0] *= sc0; o[nt][1] *= sc0; o[nt][2] *= sc1; o[nt][3] *= sc1;
        }
        __syncwarp();
        // O += P @ V
        const float* Vsm = Vp[bf];
        #pragma unroll
        for (int ks = 0; ks < 8; ks++) {
            uint32_t af[4];
            const float* ap = Ps + (w * 16 + gp) * FA_KP + ks * 8 + qd;
            af[0] = rna_tf32(ap[0]); af[1] = rna_tf32(ap[8 * FA_KP]);
            af[2] = rna_tf32(ap[4]); af[3] = rna_tf32(ap[8 * FA_KP + 4]);
            #pragma unroll
            for (int nt = 0; nt < 8; nt++) {
                uint32_t bfr[2];
                const float* bp = Vsm + (ks * 8 + qd) * FA_VP + nt * 8 + gp;
                bfr[0] = rna_tf32(bp[0]); bfr[1] = rna_tf32(bp[4 * FA_VP]);
                mma_tf32(o[nt], af, bfr);
            }
        }
        __syncthreads();
    }

    float inv0 = 1.f / l0, inv1 = 1.f / l1;
    int r0 = q0 + w * 16 + gp;
    float* O0 = O + (size_t)(b * T + r0) * D + h * HD;
    float* O1 = O0 + (size_t)8 * D;
    #pragma unroll
    for (int nt = 0; nt < 8; nt++) {
        int c = nt * 8 + 2 * qd;
        *(float2*)(O0 + c) = make_float2(o[nt][0] * inv0, o[nt][1] * inv0);
        *(float2*)(O1 + c) = make_float2(o[nt][2] * inv1, o[nt][3] * inv1);
    }
}

// ======================= transpose (weights: [K,N] -> [N,K]) =======================
__global__ __launch_bounds__(256) void transpose_kernel(
    const float* __restrict__ in, float* __restrict__ out, int K, int N)
{
    __shared__ float tile[32][33];
    int k0 = blockIdx.y * 32, n0 = blockIdx.x * 32;
    int tx = threadIdx.x, ty = threadIdx.y;
    #pragma unroll
    for (int i = 0; i < 32; i += 8)
        tile[ty + i][tx] = in[(size_t)(k0 + ty + i) * N + n0 + tx];
    __syncthreads();
    #pragma unroll
    for (int i = 0; i < 32; i += 8)
        out[(size_t)(n0 + ty + i) * K + k0 + tx] = tile[tx][ty + i];
}

// ======================= LayerNorm =======================
__device__ __forceinline__ float block_sum256(float v, float* red) {
    int t = threadIdx.x;
    #pragma unroll
    for (int o = 16; o > 0; o >>= 1) v += __shfl_xor_sync(0xffffffffu, v, o);
    if ((t & 31) == 0) red[t >> 5] = v;
    __syncthreads();
    if (t < 32) {
        float s = (t < 8) ? red[t] : 0.0f;
        #pragma unroll
        for (int o = 4; o > 0; o >>= 1) s += __shfl_xor_sync(0xffffffffu, s, o);
        if (t == 0) red[0] = s;
    }
    __syncthreads();
    float r = red[0];
    __syncthreads();
    return r;
}

__global__ __launch_bounds__(256) void ln_kernel(
    const float* __restrict__ x, const float* __restrict__ g,
    const float* __restrict__ b, float* __restrict__ out)
{
    __shared__ float red[32];
    int r = blockIdx.x, t = threadIdx.x;
    const float* xr = x + (size_t)r * D;
    float4 v = *(const float4*)(xr + t * 4);
    float mu = block_sum256(v.x + v.y + v.z + v.w, red) * (1.0f / D);
    float dx = v.x - mu, dy = v.y - mu, dz = v.z - mu, dw = v.w - mu;
    float var = block_sum256(dx * dx + dy * dy + dz * dz + dw * dw, red) * (1.0f / D);
    float inv = rsqrtf(var + 1e-5f);
    float4 gv = *(const float4*)(g + t * 4);
    float4 bv = *(const float4*)(b + t * 4);
    float4 o;
    o.x = dx * inv * gv.x + bv.x; o.y = dy * inv * gv.y + bv.y;
    o.z = dz * inv * gv.z + bv.z; o.w = dw * inv * gv.w + bv.w;
    *(float4*)(out + (size_t)r * D + t * 4) = o;
}

// ======================= launch =======================
static float* sym_addr(const void* sym) {
    void* p = nullptr;
    cudaGetSymbolAddress(&p, sym);
    return (float*)p;
}

extern "C" void kernel_launch(void* const* d_in, const int* in_sizes, int n_in,
                              void* d_out, int out_size)
{
    const float* x     = (const float*)d_in[0];
    const float* w_qkv = (const float*)d_in[1];
    const float* b_qkv = (const float*)d_in[2];
    const float* w_fc  = (const float*)d_in[3];
    const float* b_fc  = (const float*)d_in[4];
    const float* ln1_g = (const float*)d_in[5];
    const float* ln1_b = (const float*)d_in[6];
    const float* ln2_g = (const float*)d_in[7];
    const float* ln2_b = (const float*)d_in[8];
    const float* w1    = (const float*)d_in[9];
    const float* b1    = (const float*)d_in[10];
    const float* w2    = (const float*)d_in[11];
    const float* b2    = (const float*)d_in[12];
    float* out = (float*)d_out;

    float* p_h     = sym_addr(g_h);
    float* p_qkv   = sym_addr(g_qkv);
    float* p_attn  = sym_addr(g_attn);
    float* p_x1    = sym_addr(g_x1);
    float* p_h2    = sym_addr(g_h2);
    float* p_ffn   = sym_addr(g_ffn);
    float* p_wqkvT = sym_addr(g_wqkvT);
    float* p_wfcT  = sym_addr(g_wfcT);
    float* p_w1T   = sym_addr(g_w1T);
    float* p_w2T   = sym_addr(g_w2T);

    cudaFuncSetAttribute(gemm_mma<false, false>, cudaFuncAttributeMaxDynamicSharedMemorySize, GEMM_SMEM);
    cudaFuncSetAttribute(gemm_mma<false, true>,  cudaFuncAttributeMaxDynamicSharedMemorySize, GEMM_SMEM);
    cudaFuncSetAttribute(gemm_mma<true,  false>, cudaFuncAttributeMaxDynamicSharedMemorySize, GEMM_SMEM);
    cudaFuncSetAttribute(flash_kernel, cudaFuncAttributeMaxDynamicSharedMemorySize, FA_SMEM_B);

    // weight transposes: [K,N] -> [N,K]
    transpose_kernel<<<dim3(3 * D / 32, D / 32), dim3(32, 8)>>>(w_qkv, p_wqkvT, D, 3 * D);
    transpose_kernel<<<dim3(D / 32, D / 32),     dim3(32, 8)>>>(w_fc,  p_wfcT,  D, D);
    transpose_kernel<<<dim3(4 * D / 32, D / 32), dim3(32, 8)>>>(w1,    p_w1T,   D, 4 * D);
    transpose_kernel<<<dim3(D / 32, 4 * D / 32), dim3(32, 8)>>>(w2,    p_w2T,   4 * D, D);

    // 1. h = LN1(x)
    ln_kernel<<<ROWS, 256>>>(x, ln1_g, ln1_b, p_h);
    // 2. qkv = h @ w_qkv + b_qkv
    gemm_mma<false, false><<<dim3(3 * D / 128, ROWS / 128), 256, GEMM_SMEM>>>(
        p_h, p_wqkvT, b_qkv, nullptr, p_qkv, ROWS, 3 * D, D);
    // 3. fused attention
    flash_kernel<<<dim3(T / 64, BHCNT), 128, FA_SMEM_B>>>(p_qkv, p_attn);
    // 4. x1 = x + attn @ w_fc + b_fc
    gemm_mma<false, true><<<dim3(D / 128, ROWS / 128), 256, GEMM_SMEM>>>(
        p_attn, p_wfcT, b_fc, x, p_x1, ROWS, D, D);
    // 5. h2 = LN2(x1)
    ln_kernel<<<ROWS, 256>>>(p_x1, ln2_g, ln2_b, p_h2);
    // 6. ffn = gelu(h2 @ w1 + b1)
    gemm_mma<true, false><<<dim3(4 * D / 128, ROWS / 128), 256, GEMM_SMEM>>>(
        p_h2, p_w1T, b1, nullptr, p_ffn, ROWS, 4 * D, D);
    // 7. out = x1 + ffn @ w2 + b2
    gemm_mma<false, true><<<dim3(D / 128, ROWS / 128), 256, GEMM_SMEM>>>(
        p_ffn, p_w2T, b2, p_x1, out, ROWS, D, 4 * D);
}

// round 5
// speedup vs baseline: 3.8539x; 1.0440x over previous
#include <cuda_runtime.h>
#include <cuda_bf16.h>
#include <math.h>
#include <stdint.h>

// Problem constants
#define BATCH 2
#define T     2048
#define D     1024
#define NH    16
#define HD    64
#define ROWS  (BATCH * T)        // 4096
#define BHCNT (BATCH * NH)       // 32

// ---------------- scratch (device globals; no allocation allowed) -------------
__device__ float g_h    [(size_t)ROWS * D];
__device__ float g_qkv  [(size_t)ROWS * 3 * D];
__device__ float g_attn [(size_t)ROWS * D];
__device__ float g_x1   [(size_t)ROWS * D];
__device__ float g_h2   [(size_t)ROWS * D];
__device__ float g_ffn  [(size_t)ROWS * 4 * D];

// ======================= common helpers =======================
__device__ __forceinline__ uint32_t smem_u32(const void* p) {
    uint32_t a;
    asm("{ .reg .u64 t; cvta.to.shared.u64 t, %1; cvt.u32.u64 %0, t; }" : "=r"(a) : "l"(p));
    return a;
}
__device__ __forceinline__ void cp_async16(uint32_t s, const void* g) {
    asm volatile("cp.async.ca.shared.global [%0], [%1], 16;" :: "r"(s), "l"(g));
}
__device__ __forceinline__ void cp_commit() {
    asm volatile("cp.async.commit_group;" ::: "memory");
}
template<int N>
__device__ __forceinline__ void cp_wait() {
    asm volatile("cp.async.wait_group %0;" :: "n"(N) : "memory");
}
__device__ __forceinline__ uint32_t rna_tf32(float v) {
    return __float_as_uint(v) + 0x1000u;   // round-to-nearest-away into tf32 field
}
__device__ __forceinline__ void mma_tf32(float* c, const uint32_t* a, const uint32_t* b) {
    asm volatile(
        "mma.sync.aligned.m16n8k8.row.col.f32.tf32.tf32.f32 "
        "{%0,%1,%2,%3}, {%4,%5,%6,%7}, {%8,%9}, {%0,%1,%2,%3};"
        : "+f"(c[0]), "+f"(c[1]), "+f"(c[2]), "+f"(c[3])
        : "r"(a[0]), "r"(a[1]), "r"(a[2]), "r"(a[3]), "r"(b[0]), "r"(b[1]));
}

// ======================= mma.sync tf32 GEMM (B in natural [K,N]) =======================
// CTA 128x128, BK=32, 4 warps (2x2), warp tile 64x64, double-buffered cp.async.
// A smem: [128][36] (M-major, K contig);  B smem: [32][136] (K-major, N contig).
#define ASTR 36
#define BSTR 136
#define A_TILE_B (128 * ASTR * 4)              // 18432
#define B_TILE_B (32 * BSTR * 4)               // 17408
#define STG_B    (A_TILE_B + B_TILE_B)         // 35840
#define GEMM_SMEM (2 * STG_B)                  // 71680

template<bool GELU, bool RES>
__global__ __launch_bounds__(128, 2) void gemm_mma(
    const float* __restrict__ A, const float* __restrict__ B,
    const float* __restrict__ bias, const float* __restrict__ res,
    float* __restrict__ C, int M, int N, int K)
{
    extern __shared__ char smem[];
    const uint32_t sb = smem_u32(smem);
    int t = threadIdx.x;
    int wid = t >> 5, lane = t & 31;
    int wm = wid >> 1, wn = wid & 1;              // warp grid 2x2, warp tile 64x64
    int group = lane >> 2, qd = lane & 3;
    int m0 = blockIdx.y * 128, n0 = blockIdx.x * 128;

    auto load_chunk = [&](int c, int buf) {
        uint32_t sa = sb + buf * STG_B;
        uint32_t sbB = sa + A_TILE_B;
        const float* Ag = A + (size_t)m0 * K + c * 32;
        const float* Bg = B + (size_t)(c * 32) * N + n0;
        #pragma unroll
        for (int j = 0; j < 8; j++) {
            int idx = t + j * 128;
            int ar = idx >> 3, asg = idx & 7;      // A: 128 rows x 8 segs
            cp_async16(sa + ar * (ASTR * 4) + asg * 16, Ag + (size_t)ar * K + asg * 4);
            int br = idx >> 5, bsg = idx & 31;     // B: 32 rows x 32 segs
            cp_async16(sbB + br * (BSTR * 4) + bsg * 16, Bg + (size_t)br * N + bsg * 4);
        }
        cp_commit();
    };

    float acc[4][8][4] = {};
    int nch = K / 32;

    load_chunk(0, 0);
    for (int c = 0; c < nch; c++) {
        if (c + 1 < nch) { load_chunk(c + 1, (c + 1) & 1); cp_wait<1>(); }
        else             { cp_wait<0>(); }
        __syncthreads();

        const float* As = (const float*)(smem + (c & 1) * STG_B);
        const float* Bs = (const float*)(smem + (c & 1) * STG_B + A_TILE_B);
        #pragma unroll
        for (int s = 0; s < 4; s++) {
            uint32_t af[4][4], bf[8][2];
            #pragma unroll
            for (int mt = 0; mt < 4; mt++) {
                const float* ap = As + (wm * 64 + mt * 16 + group) * ASTR + s * 8 + qd;
                af[mt][0] = rna_tf32(ap[0]);
                af[mt][1] = rna_tf32(ap[8 * ASTR]);
                af[mt][2] = rna_tf32(ap[4]);
                af[mt][3] = rna_tf32(ap[8 * ASTR + 4]);
            }
            #pragma unroll
            for (int nt = 0; nt < 8; nt++) {
                const float* bp = Bs + (s * 8 + qd) * BSTR + wn * 64 + nt * 8 + group;
                bf[nt][0] = rna_tf32(bp[0]);
                bf[nt][1] = rna_tf32(bp[4 * BSTR]);
            }
            #pragma unroll
            for (int mt = 0; mt < 4; mt++)
                #pragma unroll
                for (int nt = 0; nt < 8; nt++)
                    mma_tf32(acc[mt][nt], af[mt], bf[nt]);
        }
        __syncthreads();
    }

    #pragma unroll
    for (int nt = 0; nt < 8; nt++) {
        int n = n0 + wn * 64 + nt * 8 + qd * 2;
        float2 bv = *(const float2*)(bias + n);
        #pragma unroll
        for (int mt = 0; mt < 4; mt++) {
            int m = m0 + wm * 64 + mt * 16 + group;
            float* c4 = acc[mt][nt];
            float2 v0 = make_float2(c4[0] + bv.x, c4[1] + bv.y);
            float2 v1 = make_float2(c4[2] + bv.x, c4[3] + bv.y);
            if (GELU) {
                v0.x *= normcdff(v0.x); v0.y *= normcdff(v0.y);
                v1.x *= normcdff(v1.x); v1.y *= normcdff(v1.y);
            }
            if (RES) {
                float2 r0 = *(const float2*)(res + (size_t)m * N + n);
                float2 r1 = *(const float2*)(res + (size_t)(m + 8) * N + n);
                v0.x += r0.x; v0.y += r0.y; v1.x += r1.x; v1.y += r1.y;
            }
            *(float2*)(C + (size_t)m * N + n) = v0;
            *(float2*)(C + (size_t)(m + 8) * N + n) = v1;
        }
    }
}

// ======================= flash attention (tf32 mma) =======================
#define FA_KP 68
#define FA_VP 72
#define FA_SMEM_B ((3 * 64 * FA_KP + 2 * 64 * FA_VP) * 4)   // 89088 B

__global__ __launch_bounds__(128) void flash_kernel(
    const float* __restrict__ qkv, float* __restrict__ O)
{
    extern __shared__ float sm[];
    float* Ps = sm;
    const uint32_t sb = smem_u32(sm);
    const uint32_t kB[2] = { sb + 64u * FA_KP * 4, sb + 2u * 64 * FA_KP * 4 };
    const uint32_t vB[2] = { sb + 3u * 64 * FA_KP * 4,
                             sb + 3u * 64 * FA_KP * 4 + 64u * FA_VP * 4 };
    const float* Kp[2] = { sm + 64 * FA_KP, sm + 2 * 64 * FA_KP };
    const float* Vp[2] = { sm + 3 * 64 * FA_KP, sm + 3 * 64 * FA_KP + 64 * FA_VP };

    int qt = blockIdx.x, bh = blockIdx.y;
    int b = bh >> 4, h = bh & 15;
    int q0 = qt * 64;
    int t = threadIdx.x, w = t >> 5, lane = t & 31, gp = lane >> 2, qd = lane & 3;

    for (int i = t; i < 64 * 16; i += 128) {
        int row = i >> 4, sg = i & 15;
        *(float4*)(Ps + row * FA_KP + sg * 4) =
            *(const float4*)(qkv + (size_t)(b * T + q0 + row) * (3 * D) + h * HD + sg * 4);
    }
    __syncthreads();
    uint32_t qf[8][4];
    #pragma unroll
    for (int ks = 0; ks < 8; ks++) {
        const float* ap = Ps + (w * 16 + gp) * FA_KP + ks * 8 + qd;
        qf[ks][0] = rna_tf32(ap[0]);
        qf[ks][1] = rna_tf32(ap[8 * FA_KP]);
        qf[ks][2] = rna_tf32(ap[4]);
        qf[ks][3] = rna_tf32(ap[8 * FA_KP + 4]);
    }
    __syncthreads();

    auto load_kv = [&](int kt, int bf) {
        const float* kg = qkv + (size_t)(b * T + kt * 64) * (3 * D) + D + h * HD;
        #pragma unroll
        for (int i = 0; i < 8; i++) {
            int idx = t + i * 128;
            int row = idx >> 4, sg = idx & 15;
            const float* kr = kg + (size_t)row * (3 * D) + sg * 4;
            cp_async16(kB[bf] + row * (FA_KP * 4) + sg * 16, kr);
            cp_async16(vB[bf] + row * (FA_VP * 4) + sg * 16, kr + D);
        }
        cp_commit();
    };

    float m0 = -INFINITY, m1 = -INFINITY, l0 = 0.f, l1 = 0.f;
    float o[8][4] = {};

    load_kv(0, 0);
    for (int kt = 0; kt <= qt; kt++) {
        int bf = kt & 1;
        if (kt < qt) { load_kv(kt + 1, bf ^ 1); cp_wait<1>(); }
        else         { cp_wait<0>(); }
        __syncthreads();

        float s[8][4] = {};
        const float* Ksm = Kp[bf];
        #pragma unroll
        for (int ks = 0; ks < 8; ks++) {
            #pragma unroll
            for (int nt = 0; nt < 8; nt++) {
                uint32_t bfr[2];
                const float* bp = Ksm + (nt * 8 + gp) * FA_KP + ks * 8 + qd;
                bfr[0] = rna_tf32(bp[0]); bfr[1] = rna_tf32(bp[4]);
                mma_tf32(s[nt], qf[ks], bfr);
            }
        }
        bool diag = (kt == qt);
        int r0l = w * 16 + gp;
        #pragma unroll
        for (int nt = 0; nt < 8; nt++) {
            int c = nt * 8 + 2 * qd;
            s[nt][0] *= 0.125f; s[nt][1] *= 0.125f;
            s[nt][2] *= 0.125f; s[nt][3] *= 0.125f;
            if (diag) {
                if (c     > r0l)     s[nt][0] = -INFINITY;
                if (c + 1 > r0l)     s[nt][1] = -INFINITY;
                if (c     > r0l + 8) s[nt][2] = -INFINITY;
                if (c + 1 > r0l + 8) s[nt][3] = -INFINITY;
            }
        }
        float mx0 = -INFINITY, mx1 = -INFINITY;
        #pragma unroll
        for (int nt = 0; nt < 8; nt++) {
            mx0 = fmaxf(mx0, fmaxf(s[nt][0], s[nt][1]));
            mx1 = fmaxf(mx1, fmaxf(s[nt][2], s[nt][3]));
        }
        mx0 = fmaxf(mx0, __shfl_xor_sync(~0u, mx0, 1));
        mx0 = fmaxf(mx0, __shfl_xor_sync(~0u, mx0, 2));
        mx1 = fmaxf(mx1, __shfl_xor_sync(~0u, mx1, 1));
        mx1 = fmaxf(mx1, __shfl_xor_sync(~0u, mx1, 2));
        float mn0 = fmaxf(m0, mx0), mn1 = fmaxf(m1, mx1);
        float sc0 = __expf(m0 - mn0), sc1 = __expf(m1 - mn1);
        m0 = mn0; m1 = mn1;
        float ls0 = 0.f, ls1 = 0.f;
        float* Pw = Ps + (w * 16 + gp) * FA_KP + 2 * qd;
        #pragma unroll
        for (int nt = 0; nt < 8; nt++) {
            float p0 = __expf(s[nt][0] - mn0), p1 = __expf(s[nt][1] - mn0);
            float p2 = __expf(s[nt][2] - mn1), p3 = __expf(s[nt][3] - mn1);
            ls0 += p0 + p1; ls1 += p2 + p3;
            *(float2*)(Pw + nt * 8) = make_float2(p0, p1);
            *(float2*)(Pw + 8 * FA_KP + nt * 8) = make_float2(p2, p3);
        }
        ls0 += __shfl_xor_sync(~0u, ls0, 1); ls0 += __shfl_xor_sync(~0u, ls0, 2);
        ls1 += __shfl_xor_sync(~0u, ls1, 1); ls1 += __shfl_xor_sync(~0u, ls1, 2);
        l0 = l0 * sc0 + ls0; l1 = l1 * sc1 + ls1;
        #pragma unroll
        for (int nt = 0; nt < 8; nt++) {
            o[nt][0] *= sc0; o[nt][1] *= sc0; o[nt][2] *= sc1; o[nt][3] *= sc1;
        }
        __syncwarp();
        const float* Vsm = Vp[bf];
        #pragma unroll
        for (int ks = 0; ks < 8; ks++) {
            uint32_t af[4];
            const float* ap = Ps + (w * 16 + gp) * FA_KP + ks * 8 + qd;
            af[0] = rna_tf32(ap[0]); af[1] = rna_tf32(ap[8 * FA_KP]);
            af[2] = rna_tf32(ap[4]); af[3] = rna_tf32(ap[8 * FA_KP + 4]);
            #pragma unroll
            for (int nt = 0; nt < 8; nt++) {
                uint32_t bfr[2];
                const float* bp = Vsm + (ks * 8 + qd) * FA_VP + nt * 8 + gp;
                bfr[0] = rna_tf32(bp[0]); bfr[1] = rna_tf32(bp[4 * FA_VP]);
                mma_tf32(o[nt], af, bfr);
            }
        }
        __syncthreads();
    }

    float inv0 = 1.f / l0, inv1 = 1.f / l1;
    int r0 = q0 + w * 16 + gp;
    float* O0 = O + (size_t)(b * T + r0) * D + h * HD;
    float* O1 = O0 + (size_t)8 * D;
    #pragma unroll
    for (int nt = 0; nt < 8; nt++) {
        int c = nt * 8 + 2 * qd;
        *(float2*)(O0 + c) = make_float2(o[nt][0] * inv0, o[nt][1] * inv0);
        *(float2*)(O1 + c) = make_float2(o[nt][2] * inv1, o[nt][3] * inv1);
    }
}

// ======================= LayerNorm =======================
__device__ __forceinline__ float block_sum256(float v, float* red) {
    int t = threadIdx.x;
    #pragma unroll
    for (int o = 16; o > 0; o >>= 1) v += __shfl_xor_sync(0xffffffffu, v, o);
    if ((t & 31) == 0) red[t >> 5] = v;
    __syncthreads();
    if (t < 32) {
        float s = (t < 8) ? red[t] : 0.0f;
        #pragma unroll
        for (int o = 4; o > 0; o >>= 1) s += __shfl_xor_sync(0xffffffffu, s, o);
        if (t == 0) red[0] = s;
    }
    __syncthreads();
    float r = red[0];
    __syncthreads();
    return r;
}

__global__ __launch_bounds__(256) void ln_kernel(
    const float* __restrict__ x, const float* __restrict__ g,
    const float* __restrict__ b, float* __restrict__ out)
{
    __shared__ float red[32];
    int r = blockIdx.x, t = threadIdx.x;
    const float* xr = x + (size_t)r * D;
    float4 v = *(const float4*)(xr + t * 4);
    float mu = block_sum256(v.x + v.y + v.z + v.w, red) * (1.0f / D);
    float dx = v.x - mu, dy = v.y - mu, dz = v.z - mu, dw = v.w - mu;
    float var = block_sum256(dx * dx + dy * dy + dz * dz + dw * dw, red) * (1.0f / D);
    float inv = rsqrtf(var + 1e-5f);
    float4 gv = *(const float4*)(g + t * 4);
    float4 bv = *(const float4*)(b + t * 4);
    float4 o;
    o.x = dx * inv * gv.x + bv.x; o.y = dy * inv * gv.y + bv.y;
    o.z = dz * inv * gv.z + bv.z; o.w = dw * inv * gv.w + bv.w;
    *(float4*)(out + (size_t)r * D + t * 4) = o;
}

// ======================= launch =======================
static float* sym_addr(const void* sym) {
    void* p = nullptr;
    cudaGetSymbolAddress(&p, sym);
    return (float*)p;
}

extern "C" void kernel_launch(void* const* d_in, const int* in_sizes, int n_in,
                              void* d_out, int out_size)
{
    const float* x     = (const float*)d_in[0];
    const float* w_qkv = (const float*)d_in[1];
    const float* b_qkv = (const float*)d_in[2];
    const float* w_fc  = (const float*)d_in[3];
    const float* b_fc  = (const float*)d_in[4];
    const float* ln1_g = (const float*)d_in[5];
    const float* ln1_b = (const float*)d_in[6];
    const float* ln2_g = (const float*)d_in[7];
    const float* ln2_b = (const float*)d_in[8];
    const float* w1    = (const float*)d_in[9];
    const float* b1    = (const float*)d_in[10];
    const float* w2    = (const float*)d_in[11];
    const float* b2    = (const float*)d_in[12];
    float* out = (float*)d_out;

    float* p_h    = sym_addr(g_h);
    float* p_qkv  = sym_addr(g_qkv);
    float* p_attn = sym_addr(g_attn);
    float* p_x1   = sym_addr(g_x1);
    float* p_h2   = sym_addr(g_h2);
    float* p_ffn  = sym_addr(g_ffn);

    cudaFuncSetAttribute(gemm_mma<false, false>, cudaFuncAttributeMaxDynamicSharedMemorySize, GEMM_SMEM);
    cudaFuncSetAttribute(gemm_mma<false, true>,  cudaFuncAttributeMaxDynamicSharedMemorySize, GEMM_SMEM);
    cudaFuncSetAttribute(gemm_mma<true,  false>, cudaFuncAttributeMaxDynamicSharedMemorySize, GEMM_SMEM);
    cudaFuncSetAttribute(flash_kernel, cudaFuncAttributeMaxDynamicSharedMemorySize, FA_SMEM_B);

    // 1. h = LN1(x)
    ln_kernel<<<ROWS, 256>>>(x, ln1_g, ln1_b, p_h);
    // 2. qkv = h @ w_qkv + b_qkv
    gemm_mma<false, false><<<dim3(3 * D / 128, ROWS / 128), 128, GEMM_SMEM>>>(
        p_h, w_qkv, b_qkv, nullptr, p_qkv, ROWS, 3 * D, D);
    // 3. fused attention
    flash_kernel<<<dim3(T / 64, BHCNT), 128, FA_SMEM_B>>>(p_qkv, p_attn);
    // 4. x1 = x + attn @ w_fc + b_fc
    gemm_mma<false, true><<<dim3(D / 128, ROWS / 128), 128, GEMM_SMEM>>>(
        p_attn, w_fc, b_fc, x, p_x1, ROWS, D, D);
    // 5. h2 = LN2(x1)
    ln_kernel<<<ROWS, 256>>>(p_x1, ln2_g, ln2_b, p_h2);
    // 6. ffn = gelu(h2 @ w1 + b1)
    gemm_mma<true, false><<<dim3(4 * D / 128, ROWS / 128), 128, GEMM_SMEM>>>(
        p_h2, w1, b1, nullptr, p_ffn, ROWS, 4 * D, D);
    // 7. out = x1 + ffn @ w2 + b2
    gemm_mma<false, true><<<dim3(D / 128, ROWS / 128), 128, GEMM_SMEM>>>(
        p_ffn, w2, b2, p_x1, out, ROWS, D, 4 * D);
}

// round 6
// speedup vs baseline: 5.3920x; 1.3991x over previous
#include <cuda_runtime.h>
#include <cuda_fp16.h>
#include <math.h>
#include <stdint.h>

// Problem constants
#define BATCH 2
#define T     2048
#define D     1024
#define NH    16
#define HD    64
#define ROWS  (BATCH * T)        // 4096
#define BHCNT (BATCH * NH)       // 32

// ---------------- scratch (device globals; no allocation allowed) -------------
__device__ __half g_h16  [(size_t)ROWS * D];
__device__ float  g_qkv  [(size_t)ROWS * 3 * D];
__device__ __half g_attn16[(size_t)ROWS * D];
__device__ float  g_x1   [(size_t)ROWS * D];
__device__ __half g_h216 [(size_t)ROWS * D];
__device__ __half g_ffn16[(size_t)ROWS * 4 * D];
__device__ __half g_wqkv16[(size_t)3 * D * D];   // [N,K] fp16
__device__ __half g_wfc16 [(size_t)D * D];
__device__ __half g_w116  [(size_t)4 * D * D];
__device__ __half g_w216  [(size_t)4 * D * D];

// ======================= common helpers =======================
__device__ __forceinline__ uint32_t smem_u32(const void* p) {
    uint32_t a;
    asm("{ .reg .u64 t; cvta.to.shared.u64 t, %1; cvt.u32.u64 %0, t; }" : "=r"(a) : "l"(p));
    return a;
}
__device__ __forceinline__ void cp_async16(uint32_t s, const void* g) {
    asm volatile("cp.async.ca.shared.global [%0], [%1], 16;" :: "r"(s), "l"(g));
}
__device__ __forceinline__ void cp_commit() {
    asm volatile("cp.async.commit_group;" ::: "memory");
}
template<int N>
__device__ __forceinline__ void cp_wait() {
    asm volatile("cp.async.wait_group %0;" :: "n"(N) : "memory");
}
__device__ __forceinline__ uint32_t rna_tf32(float v) {
    return __float_as_uint(v) + 0x1000u;
}
__device__ __forceinline__ void mma_tf32(float* c, const uint32_t* a, const uint32_t* b) {
    asm volatile(
        "mma.sync.aligned.m16n8k8.row.col.f32.tf32.tf32.f32 "
        "{%0,%1,%2,%3}, {%4,%5,%6,%7}, {%8,%9}, {%0,%1,%2,%3};"
        : "+f"(c[0]), "+f"(c[1]), "+f"(c[2]), "+f"(c[3])
        : "r"(a[0]), "r"(a[1]), "r"(a[2]), "r"(a[3]), "r"(b[0]), "r"(b[1]));
}
__device__ __forceinline__ void mma_f16(float* c, const uint32_t* a, const uint32_t* b) {
    asm volatile(
        "mma.sync.aligned.m16n8k16.row.col.f32.f16.f16.f32 "
        "{%0,%1,%2,%3}, {%4,%5,%6,%7}, {%8,%9}, {%0,%1,%2,%3};"
        : "+f"(c[0]), "+f"(c[1]), "+f"(c[2]), "+f"(c[3])
        : "r"(a[0]), "r"(a[1]), "r"(a[2]), "r"(a[3]), "r"(b[0]), "r"(b[1]));
}

// ======================= fp16 mma GEMM =======================
// C[M,N] = A[M,K]fp16 @ B16[N,K]fp16^T + bias(fp32), opt GELU, opt fp32 residual.
// Outputs: Cf (fp32) if non-null, Ch (fp16) if non-null.
// CTA 128x128, BK=64 halves, 4 warps 2x2 (warp tile 64x64), double-buffered cp.async.
#define HSTR 72                                   // halves per smem row
#define HT_B (128 * HSTR * 2)                     // 18432 B per tile
#define HSTG_B (2 * HT_B)                         // A+B stage = 36864
#define GEMM_SMEM (2 * HSTG_B)                    // 73728

template<bool GELU, bool RES>
__global__ __launch_bounds__(128, 2) void gemm_h(
    const __half* __restrict__ A, const __half* __restrict__ B,
    const float* __restrict__ bias, const float* __restrict__ res,
    float* __restrict__ Cf, __half* __restrict__ Ch, int M, int N, int K)
{
    extern __shared__ char smem[];
    const uint32_t sb = smem_u32(smem);
    int t = threadIdx.x;
    int wid = t >> 5, lane = t & 31;
    int wm = wid >> 1, wn = wid & 1;
    int group = lane >> 2, qd = lane & 3;
    int m0 = blockIdx.y * 128, n0 = blockIdx.x * 128;

    auto load_chunk = [&](int c, int buf) {
        uint32_t sa = sb + buf * HSTG_B;
        uint32_t sbB = sa + HT_B;
        const __half* Ag = A + (size_t)m0 * K + c * 64;
        const __half* Bg = B + (size_t)n0 * K + c * 64;
        #pragma unroll
        for (int j = 0; j < 8; j++) {
            int idx = t + j * 128;
            int r = idx >> 3, sg = idx & 7;        // 128 rows x 8 segs(16B=8 halves)
            cp_async16(sa  + r * (HSTR * 2) + sg * 16, Ag + (size_t)r * K + sg * 8);
            cp_async16(sbB + r * (HSTR * 2) + sg * 16, Bg + (size_t)r * K + sg * 8);
        }
        cp_commit();
    };

    float acc[4][8][4] = {};
    int nch = K / 64;

    load_chunk(0, 0);
    for (int c = 0; c < nch; c++) {
        if (c + 1 < nch) { load_chunk(c + 1, (c + 1) & 1); cp_wait<1>(); }
        else             { cp_wait<0>(); }
        __syncthreads();

        const __half* As = (const __half*)(smem + (c & 1) * HSTG_B);
        const __half* Bs = (const __half*)(smem + (c & 1) * HSTG_B + HT_B);
        #pragma unroll
        for (int ks = 0; ks < 4; ks++) {
            uint32_t af[4][4], bf[8][2];
            #pragma unroll
            for (int mt = 0; mt < 4; mt++) {
                const __half* ap = As + (wm * 64 + mt * 16 + group) * HSTR + ks * 16 + 2 * qd;
                af[mt][0] = *(const uint32_t*)(ap);
                af[mt][1] = *(const uint32_t*)(ap + 8 * HSTR);
                af[mt][2] = *(const uint32_t*)(ap + 8);
                af[mt][3] = *(const uint32_t*)(ap + 8 * HSTR + 8);
            }
            #pragma unroll
            for (int nt = 0; nt < 8; nt++) {
                const __half* bp = Bs + (wn * 64 + nt * 8 + group) * HSTR + ks * 16 + 2 * qd;
                bf[nt][0] = *(const uint32_t*)(bp);
                bf[nt][1] = *(const uint32_t*)(bp + 8);
            }
            #pragma unroll
            for (int mt = 0; mt < 4; mt++)
                #pragma unroll
                for (int nt = 0; nt < 8; nt++)
                    mma_f16(acc[mt][nt], af[mt], bf[nt]);
        }
        __syncthreads();
    }

    #pragma unroll
    for (int nt = 0; nt < 8; nt++) {
        int n = n0 + wn * 64 + nt * 8 + qd * 2;
        float2 bv = *(const float2*)(bias + n);
        #pragma unroll
        for (int mt = 0; mt < 4; mt++) {
            int m = m0 + wm * 64 + mt * 16 + group;
            float* c4 = acc[mt][nt];
            float2 v0 = make_float2(c4[0] + bv.x, c4[1] + bv.y);
            float2 v1 = make_float2(c4[2] + bv.x, c4[3] + bv.y);
            if (GELU) {
                v0.x *= normcdff(v0.x); v0.y *= normcdff(v0.y);
                v1.x *= normcdff(v1.x); v1.y *= normcdff(v1.y);
            }
            if (RES) {
                float2 r0 = *(const float2*)(res + (size_t)m * N + n);
                float2 r1 = *(const float2*)(res + (size_t)(m + 8) * N + n);
                v0.x += r0.x; v0.y += r0.y; v1.x += r1.x; v1.y += r1.y;
            }
            if (Cf) {
                *(float2*)(Cf + (size_t)m * N + n) = v0;
                *(float2*)(Cf + (size_t)(m + 8) * N + n) = v1;
            }
            if (Ch) {
                *(__half2*)(Ch + (size_t)m * N + n) = __floats2half2_rn(v0.x, v0.y);
                *(__half2*)(Ch + (size_t)(m + 8) * N + n) = __floats2half2_rn(v1.x, v1.y);
            }
        }
    }
}

// ======================= weight convert+transpose: fp32 [K,N] -> fp16 [N,K] ==========
__global__ __launch_bounds__(256) void convert_wT(
    const float* __restrict__ in, __half* __restrict__ out, int K, int N)
{
    __shared__ float tile[32][33];
    int k0 = blockIdx.y * 32, n0 = blockIdx.x * 32;
    int tx = threadIdx.x, ty = threadIdx.y;   // 32 x 8
    #pragma unroll
    for (int i = 0; i < 32; i += 8)
        tile[ty + i][tx] = in[(size_t)(k0 + ty + i) * N + n0 + tx];
    __syncthreads();
    #pragma unroll
    for (int i = 0; i < 32; i += 8)
        out[(size_t)(n0 + ty + i) * K + k0 + tx] = __float2half_rn(tile[tx][ty + i]);
}

// ======================= flash attention (tf32 mma; qkv fp32 in, attn fp16 out) ======
#define FA_KP 68
#define FA_VP 72
#define FA_SMEM_B ((3 * 64 * FA_KP + 2 * 64 * FA_VP) * 4)   // 89088 B

__global__ __launch_bounds__(128) void flash_kernel(
    const float* __restrict__ qkv, __half* __restrict__ O)
{
    extern __shared__ float sm[];
    float* Ps = sm;
    const uint32_t sb = smem_u32(sm);
    const uint32_t kB[2] = { sb + 64u * FA_KP * 4, sb + 2u * 64 * FA_KP * 4 };
    const uint32_t vB[2] = { sb + 3u * 64 * FA_KP * 4,
                             sb + 3u * 64 * FA_KP * 4 + 64u * FA_VP * 4 };
    const float* Kp[2] = { sm + 64 * FA_KP, sm + 2 * 64 * FA_KP };
    const float* Vp[2] = { sm + 3 * 64 * FA_KP, sm + 3 * 64 * FA_KP + 64 * FA_VP };

    int qt = blockIdx.x, bh = blockIdx.y;
    int b = bh >> 4, h = bh & 15;
    int q0 = qt * 64;
    int t = threadIdx.x, w = t >> 5, lane = t & 31, gp = lane >> 2, qd = lane & 3;

    for (int i = t; i < 64 * 16; i += 128) {
        int row = i >> 4, sg = i & 15;
        *(float4*)(Ps + row * FA_KP + sg * 4) =
            *(const float4*)(qkv + (size_t)(b * T + q0 + row) * (3 * D) + h * HD + sg * 4);
    }
    __syncthreads();
    uint32_t qf[8][4];
    #pragma unroll
    for (int ks = 0; ks < 8; ks++) {
        const float* ap = Ps + (w * 16 + gp) * FA_KP + ks * 8 + qd;
        qf[ks][0] = rna_tf32(ap[0]);
        qf[ks][1] = rna_tf32(ap[8 * FA_KP]);
        qf[ks][2] = rna_tf32(ap[4]);
        qf[ks][3] = rna_tf32(ap[8 * FA_KP + 4]);
    }
    __syncthreads();

    auto load_kv = [&](int kt, int bf) {
        const float* kg = qkv + (size_t)(b * T + kt * 64) * (3 * D) + D + h * HD;
        #pragma unroll
        for (int i = 0; i < 8; i++) {
            int idx = t + i * 128;
            int row = idx >> 4, sg = idx & 15;
            const float* kr = kg + (size_t)row * (3 * D) + sg * 4;
            cp_async16(kB[bf] + row * (FA_KP * 4) + sg * 16, kr);
            cp_async16(vB[bf] + row * (FA_VP * 4) + sg * 16, kr + D);
        }
        cp_commit();
    };

    float m0 = -INFINITY, m1 = -INFINITY, l0 = 0.f, l1 = 0.f;
    float o[8][4] = {};

    load_kv(0, 0);
    for (int kt = 0; kt <= qt; kt++) {
        int bf = kt & 1;
        if (kt < qt) { load_kv(kt + 1, bf ^ 1); cp_wait<1>(); }
        else         { cp_wait<0>(); }
        __syncthreads();

        float s[8][4] = {};
        const float* Ksm = Kp[bf];
        #pragma unroll
        for (int ks = 0; ks < 8; ks++) {
            #pragma unroll
            for (int nt = 0; nt < 8; nt++) {
                uint32_t bfr[2];
                const float* bp = Ksm + (nt * 8 + gp) * FA_KP + ks * 8 + qd;
                bfr[0] = rna_tf32(bp[0]); bfr[1] = rna_tf32(bp[4]);
                mma_tf32(s[nt], qf[ks], bfr);
            }
        }
        bool diag = (kt == qt);
        int r0l = w * 16 + gp;
        #pragma unroll
        for (int nt = 0; nt < 8; nt++) {
            int c = nt * 8 + 2 * qd;
            s[nt][0] *= 0.125f; s[nt][1] *= 0.125f;
            s[nt][2] *= 0.125f; s[nt][3] *= 0.125f;
            if (diag) {
                if (c     > r0l)     s[nt][0] = -INFINITY;
                if (c + 1 > r0l)     s[nt][1] = -INFINITY;
                if (c     > r0l + 8) s[nt][2] = -INFINITY;
                if (c + 1 > r0l + 8) s[nt][3] = -INFINITY;
            }
        }
        float mx0 = -INFINITY, mx1 = -INFINITY;
        #pragma unroll
        for (int nt = 0; nt < 8; nt++) {
            mx0 = fmaxf(mx0, fmaxf(s[nt][0], s[nt][1]));
            mx1 = fmaxf(mx1, fmaxf(s[nt][2], s[nt][3]));
        }
        mx0 = fmaxf(mx0, __shfl_xor_sync(~0u, mx0, 1));
        mx0 = fmaxf(mx0, __shfl_xor_sync(~0u, mx0, 2));
        mx1 = fmaxf(mx1, __shfl_xor_sync(~0u, mx1, 1));
        mx1 = fmaxf(mx1, __shfl_xor_sync(~0u, mx1, 2));
        float mn0 = fmaxf(m0, mx0), mn1 = fmaxf(m1, mx1);
        float sc0 = __expf(m0 - mn0), sc1 = __expf(m1 - mn1);
        m0 = mn0; m1 = mn1;
        float ls0 = 0.f, ls1 = 0.f;
        float* Pw = Ps + (w * 16 + gp) * FA_KP + 2 * qd;
        #pragma unroll
        for (int nt = 0; nt < 8; nt++) {
            float p0 = __expf(s[nt][0] - mn0), p1 = __expf(s[nt][1] - mn0);
            float p2 = __expf(s[nt][2] - mn1), p3 = __expf(s[nt][3] - mn1);
            ls0 += p0 + p1; ls1 += p2 + p3;
            *(float2*)(Pw + nt * 8) = make_float2(p0, p1);
            *(float2*)(Pw + 8 * FA_KP + nt * 8) = make_float2(p2, p3);
        }
        ls0 += __shfl_xor_sync(~0u, ls0, 1); ls0 += __shfl_xor_sync(~0u, ls0, 2);
        ls1 += __shfl_xor_sync(~0u, ls1, 1); ls1 += __shfl_xor_sync(~0u, ls1, 2);
        l0 = l0 * sc0 + ls0; l1 = l1 * sc1 + ls1;
        #pragma unroll
        for (int nt = 0; nt < 8; nt++) {
            o[nt][0] *= sc0; o[nt][1] *= sc0; o[nt][2] *= sc1; o[nt][3] *= sc1;
        }
        __syncwarp();
        const float* Vsm = Vp[bf];
        #pragma unroll
        for (int ks = 0; ks < 8; ks++) {
            uint32_t af[4];
            const float* ap = Ps + (w * 16 + gp) * FA_KP + ks * 8 + qd;
            af[0] = rna_tf32(ap[0]); af[1] = rna_tf32(ap[8 * FA_KP]);
            af[2] = rna_tf32(ap[4]); af[3] = rna_tf32(ap[8 * FA_KP + 4]);
            #pragma unroll
            for (int nt = 0; nt < 8; nt++) {
                uint32_t bfr[2];
                const float* bp = Vsm + (ks * 8 + qd) * FA_VP + nt * 8 + gp;
                bfr[0] = rna_tf32(bp[0]); bfr[1] = rna_tf32(bp[4 * FA_VP]);
                mma_tf32(o[nt], af, bfr);
            }
        }
        __syncthreads();
    }

    float inv0 = 1.f / l0, inv1 = 1.f / l1;
    int r0 = q0 + w * 16 + gp;
    __half* O0 = O + (size_t)(b * T + r0) * D + h * HD;
    __half* O1 = O0 + (size_t)8 * D;
    #pragma unroll
    for (int nt = 0; nt < 8; nt++) {
        int c = nt * 8 + 2 * qd;
        *(__half2*)(O0 + c) = __floats2half2_rn(o[nt][0] * inv0, o[nt][1] * inv0);
        *(__half2*)(O1 + c) = __floats2half2_rn(o[nt][2] * inv1, o[nt][3] * inv1);
    }
}

// ======================= LayerNorm (fp32 in, fp16 out) =======================
__device__ __forceinline__ float block_sum256(float v, float* red) {
    int t = threadIdx.x;
    #pragma unroll
    for (int o = 16; o > 0; o >>= 1) v += __shfl_xor_sync(0xffffffffu, v, o);
    if ((t & 31) == 0) red[t >> 5] = v;
    __syncthreads();
    if (t < 32) {
        float s = (t < 8) ? red[t] : 0.0f;
        #pragma unroll
        for (int o = 4; o > 0; o >>= 1) s += __shfl_xor_sync(0xffffffffu, s, o);
        if (t == 0) red[0] = s;
    }
    __syncthreads();
    float r = red[0];
    __syncthreads();
    return r;
}

__global__ __launch_bounds__(256) void ln_kernel(
    const float* __restrict__ x, const float* __restrict__ g,
    const float* __restrict__ b, __half* __restrict__ out)
{
    __shared__ float red[32];
    int r = blockIdx.x, t = threadIdx.x;
    const float* xr = x + (size_t)r * D;
    float4 v = *(const float4*)(xr + t * 4);
    float mu = block_sum256(v.x + v.y + v.z + v.w, red) * (1.0f / D);
    float dx = v.x - mu, dy = v.y - mu, dz = v.z - mu, dw = v.w - mu;
    float var = block_sum256(dx * dx + dy * dy + dz * dz + dw * dw, red) * (1.0f / D);
    float inv = rsqrtf(var + 1e-5f);
    float4 gv = *(const float4*)(g + t * 4);
    float4 bv = *(const float4*)(b + t * 4);
    __half2 o01 = __floats2half2_rn(dx * inv * gv.x + bv.x, dy * inv * gv.y + bv.y);
    __half2 o23 = __floats2half2_rn(dz * inv * gv.z + bv.z, dw * inv * gv.w + bv.w);
    uint2 pk = make_uint2(*(uint32_t*)&o01, *(uint32_t*)&o23);
    *(uint2*)(out + (size_t)r * D + t * 4) = pk;
}

// ======================= launch =======================
template<typename Tp>
static Tp* sym_addr(const void* sym) {
    void* p = nullptr;
    cudaGetSymbolAddress(&p, sym);
    return (Tp*)p;
}

extern "C" void kernel_launch(void* const* d_in, const int* in_sizes, int n_in,
                              void* d_out, int out_size)
{
    const float* x     = (const float*)d_in[0];
    const float* w_qkv = (const float*)d_in[1];
    const float* b_qkv = (const float*)d_in[2];
    const float* w_fc  = (const float*)d_in[3];
    const float* b_fc  = (const float*)d_in[4];
    const float* ln1_g = (const float*)d_in[5];
    const float* ln1_b = (const float*)d_in[6];
    const float* ln2_g = (const float*)d_in[7];
    const float* ln2_b = (const float*)d_in[8];
    const float* w1    = (const float*)d_in[9];
    const float* b1    = (const float*)d_in[10];
    const float* w2    = (const float*)d_in[11];
    const float* b2    = (const float*)d_in[12];
    float* out = (float*)d_out;

    __half* p_h16   = sym_addr<__half>(g_h16);
    float*  p_qkv   = sym_addr<float>(g_qkv);
    __half* p_attn  = sym_addr<__half>(g_attn16);
    float*  p_x1    = sym_addr<float>(g_x1);
    __half* p_h216  = sym_addr<__half>(g_h216);
    __half* p_ffn   = sym_addr<__half>(g_ffn16);
    __half* p_wqkv  = sym_addr<__half>(g_wqkv16);
    __half* p_wfc   = sym_addr<__half>(g_wfc16);
    __half* p_w1    = sym_addr<__half>(g_w116);
    __half* p_w2    = sym_addr<__half>(g_w216);

    cudaFuncSetAttribute(gemm_h<false, false>, cudaFuncAttributeMaxDynamicSharedMemorySize, GEMM_SMEM);
    cudaFuncSetAttribute(gemm_h<false, true>,  cudaFuncAttributeMaxDynamicSharedMemorySize, GEMM_SMEM);
    cudaFuncSetAttribute(gemm_h<true,  false>, cudaFuncAttributeMaxDynamicSharedMemorySize, GEMM_SMEM);
    cudaFuncSetAttribute(flash_kernel, cudaFuncAttributeMaxDynamicSharedMemorySize, FA_SMEM_B);

    // weight convert+transpose: fp32 [K,N] -> fp16 [N,K]
    convert_wT<<<dim3(3 * D / 32, D / 32), dim3(32, 8)>>>(w_qkv, p_wqkv, D, 3 * D);
    convert_wT<<<dim3(D / 32, D / 32),     dim3(32, 8)>>>(w_fc,  p_wfc,  D, D);
    convert_wT<<<dim3(4 * D / 32, D / 32), dim3(32, 8)>>>(w1,    p_w1,   D, 4 * D);
    convert_wT<<<dim3(D / 32, 4 * D / 32), dim3(32, 8)>>>(w2,    p_w2,   4 * D, D);

    // 1. h = LN1(x)  (fp16)
    ln_kernel<<<ROWS, 256>>>(x, ln1_g, ln1_b, p_h16);
    // 2. qkv = h @ w_qkv + b_qkv  (fp32 out for flash)
    gemm_h<false, false><<<dim3(3 * D / 128, ROWS / 128), 128, GEMM_SMEM>>>(
        p_h16, p_wqkv, b_qkv, nullptr, p_qkv, nullptr, ROWS, 3 * D, D);
    // 3. fused attention  (fp16 out)
    flash_kernel<<<dim3(T / 64, BHCNT), 128, FA_SMEM_B>>>(p_qkv, p_attn);
    // 4. x1 = x + attn @ w_fc + b_fc  (fp32)
    gemm_h<false, true><<<dim3(D / 128, ROWS / 128), 128, GEMM_SMEM>>>(
        p_attn, p_wfc, b_fc, x, p_x1, nullptr, ROWS, D, D);
    // 5. h2 = LN2(x1)  (fp16)
    ln_kernel<<<ROWS, 256>>>(p_x1, ln2_g, ln2_b, p_h216);
    // 6. ffn = gelu(h2 @ w1 + b1)  (fp16 only)
    gemm_h<true, false><<<dim3(4 * D / 128, ROWS / 128), 128, GEMM_SMEM>>>(
        p_h216, p_w1, b1, nullptr, nullptr, p_ffn, ROWS, 4 * D, D);
    // 7. out = x1 + ffn @ w2 + b2  (fp32)
    gemm_h<false, true><<<dim3(D / 128, ROWS / 128), 128, GEMM_SMEM>>>(
        p_ffn, p_w2, b2, p_x1, out, nullptr, ROWS, D, 4 * D);
}

// round 8
// speedup vs baseline: 6.9068x; 1.2809x over previous
#include <cuda_runtime.h>
#include <cuda_fp16.h>
#include <math.h>
#include <stdint.h>

// Problem constants
#define BATCH 2
#define T     2048
#define D     1024
#define NH    16
#define HD    64
#define ROWS  (BATCH * T)        // 4096
#define BHCNT (BATCH * NH)       // 32

// ---------------- scratch (device globals; no allocation allowed) -------------
__device__ __half g_h16   [(size_t)ROWS * D];
__device__ __half g_qkv16 [(size_t)ROWS * 3 * D];
__device__ __half g_attn16[(size_t)ROWS * D];
__device__ float  g_x1    [(size_t)ROWS * D];
__device__ __half g_h216  [(size_t)ROWS * D];
__device__ __half g_ffn16 [(size_t)ROWS * 4 * D];
__device__ __half g_wqkv16[(size_t)3 * D * D];   // [N,K] fp16
__device__ __half g_wfc16 [(size_t)D * D];
__device__ __half g_w116  [(size_t)4 * D * D];
__device__ __half g_w216  [(size_t)4 * D * D];

// ======================= common helpers =======================
__device__ __forceinline__ uint32_t smem_u32(const void* p) {
    uint32_t a;
    asm("{ .reg .u64 t; cvta.to.shared.u64 t, %1; cvt.u32.u64 %0, t; }" : "=r"(a) : "l"(p));
    return a;
}
__device__ __forceinline__ void cp_async16(uint32_t s, const void* g) {
    asm volatile("cp.async.ca.shared.global [%0], [%1], 16;" :: "r"(s), "l"(g));
}
__device__ __forceinline__ void cp_commit() {
    asm volatile("cp.async.commit_group;" ::: "memory");
}
template<int N>
__device__ __forceinline__ void cp_wait() {
    asm volatile("cp.async.wait_group %0;" :: "n"(N) : "memory");
}
__device__ __forceinline__ void mma_f16(float* c, const uint32_t* a, const uint32_t* b) {
    asm volatile(
        "mma.sync.aligned.m16n8k16.row.col.f32.f16.f16.f32 "
        "{%0,%1,%2,%3}, {%4,%5,%6,%7}, {%8,%9}, {%0,%1,%2,%3};"
        : "+f"(c[0]), "+f"(c[1]), "+f"(c[2]), "+f"(c[3])
        : "r"(a[0]), "r"(a[1]), "r"(a[2]), "r"(a[3]), "r"(b[0]), "r"(b[1]));
}
__device__ __forceinline__ void ldsm_x4_trans(
    uint32_t& r0, uint32_t& r1, uint32_t& r2, uint32_t& r3, uint32_t addr) {
    asm volatile("ldmatrix.sync.aligned.m8n8.x4.trans.shared.b16 {%0,%1,%2,%3}, [%4];"
        : "=r"(r0), "=r"(r1), "=r"(r2), "=r"(r3) : "r"(addr));
}
__device__ __forceinline__ uint32_t packh2(float a, float b) {
    __half2 h = __floats2half2_rn(a, b);
    return *(uint32_t*)&h;
}

// ======================= fp16 mma GEMM =======================
#define HSTR 72
#define HT_B (128 * HSTR * 2)
#define HSTG_B (2 * HT_B)
#define GEMM_SMEM (2 * HSTG_B)

template<bool GELU, bool RES>
__global__ __launch_bounds__(128, 2) void gemm_h(
    const __half* __restrict__ A, const __half* __restrict__ B,
    const float* __restrict__ bias, const float* __restrict__ res,
    float* __restrict__ Cf, __half* __restrict__ Ch, int M, int N, int K)
{
    extern __shared__ char smem[];
    const uint32_t sb = smem_u32(smem);
    int t = threadIdx.x;
    int wid = t >> 5, lane = t & 31;
    int wm = wid >> 1, wn = wid & 1;
    int group = lane >> 2, qd = lane & 3;
    int m0 = blockIdx.y * 128, n0 = blockIdx.x * 128;

    auto load_chunk = [&](int c, int buf) {
        uint32_t sa = sb + buf * HSTG_B;
        uint32_t sbB = sa + HT_B;
        const __half* Ag = A + (size_t)m0 * K + c * 64;
        const __half* Bg = B + (size_t)n0 * K + c * 64;
        #pragma unroll
        for (int j = 0; j < 8; j++) {
            int idx = t + j * 128;
            int r = idx >> 3, sg = idx & 7;
            cp_async16(sa  + r * (HSTR * 2) + sg * 16, Ag + (size_t)r * K + sg * 8);
            cp_async16(sbB + r * (HSTR * 2) + sg * 16, Bg + (size_t)r * K + sg * 8);
        }
        cp_commit();
    };

    float acc[4][8][4] = {};
    int nch = K / 64;

    load_chunk(0, 0);
    for (int c = 0; c < nch; c++) {
        if (c + 1 < nch) { load_chunk(c + 1, (c + 1) & 1); cp_wait<1>(); }
        else             { cp_wait<0>(); }
        __syncthreads();

        const __half* As = (const __half*)(smem + (c & 1) * HSTG_B);
        const __half* Bs = (const __half*)(smem + (c & 1) * HSTG_B + HT_B);
        #pragma unroll
        for (int ks = 0; ks < 4; ks++) {
            uint32_t af[4][4], bf[8][2];
            #pragma unroll
            for (int mt = 0; mt < 4; mt++) {
                const __half* ap = As + (wm * 64 + mt * 16 + group) * HSTR + ks * 16 + 2 * qd;
                af[mt][0] = *(const uint32_t*)(ap);
                af[mt][1] = *(const uint32_t*)(ap + 8 * HSTR);
                af[mt][2] = *(const uint32_t*)(ap + 8);
                af[mt][3] = *(const uint32_t*)(ap + 8 * HSTR + 8);
            }
            #pragma unroll
            for (int nt = 0; nt < 8; nt++) {
                const __half* bp = Bs + (wn * 64 + nt * 8 + group) * HSTR + ks * 16 + 2 * qd;
                bf[nt][0] = *(const uint32_t*)(bp);
                bf[nt][1] = *(const uint32_t*)(bp + 8);
            }
            #pragma unroll
            for (int mt = 0; mt < 4; mt++)
                #pragma unroll
                for (int nt = 0; nt < 8; nt++)
                    mma_f16(acc[mt][nt], af[mt], bf[nt]);
        }
        __syncthreads();
    }

    #pragma unroll
    for (int nt = 0; nt < 8; nt++) {
        int n = n0 + wn * 64 + nt * 8 + qd * 2;
        float2 bv = *(const float2*)(bias + n);
        #pragma unroll
        for (int mt = 0; mt < 4; mt++) {
            int m = m0 + wm * 64 + mt * 16 + group;
            float* c4 = acc[mt][nt];
            float2 v0 = make_float2(c4[0] + bv.x, c4[1] + bv.y);
            float2 v1 = make_float2(c4[2] + bv.x, c4[3] + bv.y);
            if (GELU) {
                v0.x *= normcdff(v0.x); v0.y *= normcdff(v0.y);
                v1.x *= normcdff(v1.x); v1.y *= normcdff(v1.y);
            }
            if (RES) {
                float2 r0 = *(const float2*)(res + (size_t)m * N + n);
                float2 r1 = *(const float2*)(res + (size_t)(m + 8) * N + n);
                v0.x += r0.x; v0.y += r0.y; v1.x += r1.x; v1.y += r1.y;
            }
            if (Cf) {
                *(float2*)(Cf + (size_t)m * N + n) = v0;
                *(float2*)(Cf + (size_t)(m + 8) * N + n) = v1;
            }
            if (Ch) {
                *(__half2*)(Ch + (size_t)m * N + n) = __floats2half2_rn(v0.x, v0.y);
                *(__half2*)(Ch + (size_t)(m + 8) * N + n) = __floats2half2_rn(v1.x, v1.y);
            }
        }
    }
}

// ======================= weight convert+transpose: fp32 [K,N] -> fp16 [N,K] ==========
__global__ __launch_bounds__(256) void convert_wT(
    const float* __restrict__ in, __half* __restrict__ out, int K, int N)
{
    __shared__ float tile[32][33];
    int k0 = blockIdx.y * 32, n0 = blockIdx.x * 32;
    int tx = threadIdx.x, ty = threadIdx.y;
    #pragma unroll
    for (int i = 0; i < 32; i += 8)
        tile[ty + i][tx] = in[(size_t)(k0 + ty + i) * N + n0 + tx];
    __syncthreads();
    #pragma unroll
    for (int i = 0; i < 32; i += 8)
        out[(size_t)(n0 + ty + i) * K + k0 + tx] = __float2half_rn(tile[tx][ty + i]);
}

// ======================= flash attention (fp16 mma) =======================
// smem halves, stride 72. Q: 64x72; K,V double-buffered 64x72 each.
#define FS 72
#define FT_B (64 * FS * 2)                 // 9216 B per tile
#define FA_SMEM_B (5 * FT_B)               // Q + 2K + 2V = 46080 B

__global__ __launch_bounds__(128, 2) void flash_h(
    const __half* __restrict__ qkv, __half* __restrict__ O)
{
    extern __shared__ char sm[];
    const uint32_t sb = smem_u32(sm);
    const uint32_t qB = sb;
    const uint32_t kB[2] = { sb + FT_B, sb + 2 * FT_B };
    const uint32_t vB[2] = { sb + 3 * FT_B, sb + 4 * FT_B };

    int qt = blockIdx.x, bh = blockIdx.y;
    int b = bh >> 4, h = bh & 15;
    int q0 = qt * 64;
    int t = threadIdx.x, w = t >> 5, lane = t & 31, gp = lane >> 2, qd = lane & 3;

    // stage Q (fp16, 64 rows x 8 segs)
    {
        const __half* qg = qkv + (size_t)(b * T + q0) * (3 * D) + h * HD;
        #pragma unroll
        for (int i = 0; i < 4; i++) {
            int idx = t + i * 128;
            int row = idx >> 3, sg = idx & 7;
            cp_async16(qB + row * (FS * 2) + sg * 16, qg + (size_t)row * (3 * D) + sg * 8);
        }
        cp_commit();
    }

    auto load_kv = [&](int kt, int bf) {
        const __half* kg = qkv + (size_t)(b * T + kt * 64) * (3 * D) + D + h * HD;
        #pragma unroll
        for (int i = 0; i < 4; i++) {
            int idx = t + i * 128;
            int row = idx >> 3, sg = idx & 7;
            const __half* kr = kg + (size_t)row * (3 * D) + sg * 8;
            cp_async16(kB[bf] + row * (FS * 2) + sg * 16, kr);
            cp_async16(vB[bf] + row * (FS * 2) + sg * 16, kr + D);
        }
        cp_commit();
    };

    load_kv(0, 0);
    cp_wait<1>();            // Q ready (kv0 may still be in flight)
    __syncthreads();

    uint32_t qf[4][4];
    const __half* Qs = (const __half*)sm;
    #pragma unroll
    for (int ks = 0; ks < 4; ks++) {
        const __half* ap = Qs + (w * 16 + gp) * FS + ks * 16 + 2 * qd;
        qf[ks][0] = *(const uint32_t*)(ap);
        qf[ks][1] = *(const uint32_t*)(ap + 8 * FS);
        qf[ks][2] = *(const uint32_t*)(ap + 8);
        qf[ks][3] = *(const uint32_t*)(ap + 8 * FS + 8);
    }

    float m0 = -INFINITY, m1 = -INFINITY, l0 = 0.f, l1 = 0.f;
    float o[8][4] = {};

    for (int kt = 0; kt <= qt; kt++) {
        int bf = kt & 1;
        if (kt < qt) { load_kv(kt + 1, bf ^ 1); cp_wait<1>(); }
        else         { cp_wait<0>(); }
        __syncthreads();

        // S = Q @ K^T
        float s[8][4] = {};
        const __half* Ksm = (const __half*)(sm + (kB[bf] - sb));
        #pragma unroll
        for (int ks = 0; ks < 4; ks++) {
            #pragma unroll
            for (int nt = 0; nt < 8; nt++) {
                uint32_t bfr[2];
                const __half* bp = Ksm + (nt * 8 + gp) * FS + ks * 16 + 2 * qd;
                bfr[0] = *(const uint32_t*)(bp);
                bfr[1] = *(const uint32_t*)(bp + 8);
                mma_f16(s[nt], qf[ks], bfr);
            }
        }
        // scale + causal mask
        bool diag = (kt == qt);
        int r0l = w * 16 + gp;
        #pragma unroll
        for (int nt = 0; nt < 8; nt++) {
            int c = nt * 8 + 2 * qd;
            s[nt][0] *= 0.125f; s[nt][1] *= 0.125f;
            s[nt][2] *= 0.125f; s[nt][3] *= 0.125f;
            if (diag) {
                if (c     > r0l)     s[nt][0] = -INFINITY;
                if (c + 1 > r0l)     s[nt][1] = -INFINITY;
                if (c     > r0l + 8) s[nt][2] = -INFINITY;
                if (c + 1 > r0l + 8) s[nt][3] = -INFINITY;
            }
        }
        // online softmax
        float mx0 = -INFINITY, mx1 = -INFINITY;
        #pragma unroll
        for (int nt = 0; nt < 8; nt++) {
            mx0 = fmaxf(mx0, fmaxf(s[nt][0], s[nt][1]));
            mx1 = fmaxf(mx1, fmaxf(s[nt][2], s[nt][3]));
        }
        mx0 = fmaxf(mx0, __shfl_xor_sync(~0u, mx0, 1));
        mx0 = fmaxf(mx0, __shfl_xor_sync(~0u, mx0, 2));
        mx1 = fmaxf(mx1, __shfl_xor_sync(~0u, mx1, 1));
        mx1 = fmaxf(mx1, __shfl_xor_sync(~0u, mx1, 2));
        float mn0 = fmaxf(m0, mx0), mn1 = fmaxf(m1, mx1);
        float sc0 = __expf(m0 - mn0), sc1 = __expf(m1 - mn1);
        m0 = mn0; m1 = mn1;
        // P packed straight into fp16 A-fragments (no smem round-trip)
        uint32_t pa[8], pb[8];
        float ls0 = 0.f, ls1 = 0.f;
        #pragma unroll
        for (int nt = 0; nt < 8; nt++) {
            float p0 = __expf(s[nt][0] - mn0), p1 = __expf(s[nt][1] - mn0);
            float p2 = __expf(s[nt][2] - mn1), p3 = __expf(s[nt][3] - mn1);
            ls0 += p0 + p1; ls1 += p2 + p3;
            pa[nt] = packh2(p0, p1);
            pb[nt] = packh2(p2, p3);
        }
        ls0 += __shfl_xor_sync(~0u, ls0, 1); ls0 += __shfl_xor_sync(~0u, ls0, 2);
        ls1 += __shfl_xor_sync(~0u, ls1, 1); ls1 += __shfl_xor_sync(~0u, ls1, 2);
        l0 = l0 * sc0 + ls0; l1 = l1 * sc1 + ls1;
        #pragma unroll
        for (int nt = 0; nt < 8; nt++) {
            o[nt][0] *= sc0; o[nt][1] *= sc0; o[nt][2] *= sc1; o[nt][3] *= sc1;
        }
        // O += P @ V   (V B-frags via ldmatrix.trans)
        int sub = lane >> 3, lr = lane & 7;
        #pragma unroll
        for (int ks = 0; ks < 4; ks++) {
            uint32_t af[4] = { pa[2 * ks], pb[2 * ks], pa[2 * ks + 1], pb[2 * ks + 1] };
            #pragma unroll
            for (int np = 0; np < 4; np++) {
                int vrow = ks * 16 + (sub & 1) * 8 + lr;
                int vcol = np * 16 + (sub >> 1) * 8;
                uint32_t addr = vB[bf] + (vrow * FS + vcol) * 2;
                uint32_t b0, b1, b2, b3;
                ldsm_x4_trans(b0, b1, b2, b3, addr);
                uint32_t bf0[2] = { b0, b1 }, bf1[2] = { b2, b3 };
                mma_f16(o[2 * np], af, bf0);
                mma_f16(o[2 * np + 1], af, bf1);
            }
        }
        __syncthreads();
    }

    float inv0 = 1.f / l0, inv1 = 1.f / l1;
    int r0 = q0 + w * 16 + gp;
    __half* O0 = O + (size_t)(b * T + r0) * D + h * HD;
    __half* O1 = O0 + (size_t)8 * D;
    #pragma unroll
    for (int nt = 0; nt < 8; nt++) {
        int c = nt * 8 + 2 * qd;
        *(__half2*)(O0 + c) = __floats2half2_rn(o[nt][0] * inv0, o[nt][1] * inv0);
        *(__half2*)(O1 + c) = __floats2half2_rn(o[nt][2] * inv1, o[nt][3] * inv1);
    }
}

// ======================= LayerNorm (fp32 in, fp16 out) =======================
__device__ __forceinline__ float block_sum256(float v, float* red) {
    int t = threadIdx.x;
    #pragma unroll
    for (int o = 16; o > 0; o >>= 1) v += __shfl_xor_sync(0xffffffffu, v, o);
    if ((t & 31) == 0) red[t >> 5] = v;
    __syncthreads();
    if (t < 32) {
        float s = (t < 8) ? red[t] : 0.0f;
        #pragma unroll
        for (int o = 4; o > 0; o >>= 1) s += __shfl_xor_sync(0xffffffffu, s, o);
        if (t == 0) red[0] = s;
    }
    __syncthreads();
    float r = red[0];
    __syncthreads();
    return r;
}

__global__ __launch_bounds__(256) void ln_kernel(
    const float* __restrict__ x, const float* __restrict__ g,
    const float* __restrict__ b, __half* __restrict__ out)
{
    __shared__ float red[32];
    int r = blockIdx.x, t = threadIdx.x;
    const float* xr = x + (size_t)r * D;
    float4 v = *(const float4*)(xr + t * 4);
    float mu = block_sum256(v.x + v.y + v.z + v.w, red) * (1.0f / D);
    float dx = v.x - mu, dy = v.y - mu, dz = v.z - mu, dw = v.w - mu;
    float var = block_sum256(dx * dx + dy * dy + dz * dz + dw * dw, red) * (1.0f / D);
    float inv = rsqrtf(var + 1e-5f);
    float4 gv = *(const float4*)(g + t * 4);
    float4 bv = *(const float4*)(b + t * 4);
    __half2 o01 = __floats2half2_rn(dx * inv * gv.x + bv.x, dy * inv * gv.y + bv.y);
    __half2 o23 = __floats2half2_rn(dz * inv * gv.z + bv.z, dw * inv * gv.w + bv.w);
    uint2 pk = make_uint2(*(uint32_t*)&o01, *(uint32_t*)&o23);
    *(uint2*)(out + (size_t)r * D + t * 4) = pk;
}

// ======================= launch =======================
template<typename Tp>
static Tp* sym_addr(const void* sym) {
    void* p = nullptr;
    cudaGetSymbolAddress(&p, sym);
    return (Tp*)p;
}

extern "C" void kernel_launch(void* const* d_in, const int* in_sizes, int n_in,
                              void* d_out, int out_size)
{
    const float* x     = (const float*)d_in[0];
    const float* w_qkv = (const float*)d_in[1];
    const float* b_qkv = (const float*)d_in[2];
    const float* w_fc  = (const float*)d_in[3];
    const float* b_fc  = (const float*)d_in[4];
    const float* ln1_g = (const float*)d_in[5];
    const float* ln1_b = (const float*)d_in[6];
    const float* ln2_g = (const float*)d_in[7];
    const float* ln2_b = (const float*)d_in[8];
    const float* w1    = (const float*)d_in[9];
    const float* b1    = (const float*)d_in[10];
    const float* w2    = (const float*)d_in[11];
    const float* b2    = (const float*)d_in[12];
    float* out = (float*)d_out;

    __half* p_h16  = sym_addr<__half>(g_h16);
    __half* p_qkv  = sym_addr<__half>(g_qkv16);
    __half* p_attn = sym_addr<__half>(g_attn16);
    float*  p_x1   = sym_addr<float>(g_x1);
    __half* p_h216 = sym_addr<__half>(g_h216);
    __half* p_ffn  = sym_addr<__half>(g_ffn16);
    __half* p_wqkv = sym_addr<__half>(g_wqkv16);
    __half* p_wfc  = sym_addr<__half>(g_wfc16);
    __half* p_w1   = sym_addr<__half>(g_w116);
    __half* p_w2   = sym_addr<__half>(g_w216);

    cudaFuncSetAttribute(gemm_h<false, false>, cudaFuncAttributeMaxDynamicSharedMemorySize, GEMM_SMEM);
    cudaFuncSetAttribute(gemm_h<false, true>,  cudaFuncAttributeMaxDynamicSharedMemorySize, GEMM_SMEM);
    cudaFuncSetAttribute(gemm_h<true,  false>, cudaFuncAttributeMaxDynamicSharedMemorySize, GEMM_SMEM);
    cudaFuncSetAttribute(flash_h, cudaFuncAttributeMaxDynamicSharedMemorySize, FA_SMEM_B);

    // weight convert+transpose: fp32 [K,N] -> fp16 [N,K]
    convert_wT<<<dim3(3 * D / 32, D / 32), dim3(32, 8)>>>(w_qkv, p_wqkv, D, 3 * D);
    convert_wT<<<dim3(D / 32, D / 32),     dim3(32, 8)>>>(w_fc,  p_wfc,  D, D);
    convert_wT<<<dim3(4 * D / 32, D / 32), dim3(32, 8)>>>(w1,    p_w1,   D, 4 * D);
    convert_wT<<<dim3(D / 32, 4 * D / 32), dim3(32, 8)>>>(w2,    p_w2,   4 * D, D);

    // 1. h = LN1(x)  (fp16)
    ln_kernel<<<ROWS, 256>>>(x, ln1_g, ln1_b, p_h16);
    // 2. qkv = h @ w_qkv + b_qkv  (fp16 out)
    gemm_h<false, false><<<dim3(3 * D / 128, ROWS / 128), 128, GEMM_SMEM>>>(
        p_h16, p_wqkv, b_qkv, nullptr, nullptr, p_qkv, ROWS, 3 * D, D);
    // 3. fused attention (fp16 in/out)
    flash_h<<<dim3(T / 64, BHCNT), 128, FA_SMEM_B>>>(p_qkv, p_attn);
    // 4. x1 = x + attn @ w_fc + b_fc  (fp32)
    gemm_h<false, true><<<dim3(D / 128, ROWS / 128), 128, GEMM_SMEM>>>(
        p_attn, p_wfc, b_fc, x, p_x1, nullptr, ROWS, D, D);
    // 5. h2 = LN2(x1)  (fp16)
    ln_kernel<<<ROWS, 256>>>(p_x1, ln2_g, ln2_b, p_h216);
    // 6. ffn = gelu(h2 @ w1 + b1)  (fp16)
    gemm_h<true, false><<<dim3(4 * D / 128, ROWS / 128), 128, GEMM_SMEM>>>(
        p_h216, p_w1, b1, nullptr, nullptr, p_ffn, ROWS, 4 * D, D);
    // 7. out = x1 + ffn @ w2 + b2  (fp32)
    gemm_h<false, true><<<dim3(D / 128, ROWS / 128), 128, GEMM_SMEM>>>(
        p_ffn, p_w2, b2, p_x1, out, nullptr, ROWS, D, 4 * D);
}

// round 9
// speedup vs baseline: 7.2090x; 1.0437x over previous
#include <cuda_runtime.h>
#include <cuda_fp16.h>
#include <math.h>
#include <stdint.h>

// Problem constants
#define BATCH 2
#define T     2048
#define D     1024
#define NH    16
#define HD    64
#define ROWS  (BATCH * T)        // 4096
#define BHCNT (BATCH * NH)       // 32

// ---------------- scratch (device globals; no allocation allowed) -------------
__device__ __half g_h16   [(size_t)ROWS * D];
__device__ __half g_qkv16 [(size_t)ROWS * 3 * D];
__device__ __half g_attn16[(size_t)ROWS * D];
__device__ float  g_x1    [(size_t)ROWS * D];
__device__ __half g_h216  [(size_t)ROWS * D];
__device__ __half g_ffn16 [(size_t)ROWS * 4 * D];
__device__ __half g_wqkv16[(size_t)3 * D * D];   // [N,K] fp16
__device__ __half g_wfc16 [(size_t)D * D];
__device__ __half g_w116  [(size_t)4 * D * D];
__device__ __half g_w216  [(size_t)4 * D * D];

// ======================= common helpers =======================
__device__ __forceinline__ uint32_t smem_u32(const void* p) {
    uint32_t a;
    asm("{ .reg .u64 t; cvta.to.shared.u64 t, %1; cvt.u32.u64 %0, t; }" : "=r"(a) : "l"(p));
    return a;
}
__device__ __forceinline__ void cp_async16(uint32_t s, const void* g) {
    asm volatile("cp.async.ca.shared.global [%0], [%1], 16;" :: "r"(s), "l"(g));
}
__device__ __forceinline__ void cp_commit() {
    asm volatile("cp.async.commit_group;" ::: "memory");
}
template<int N>
__device__ __forceinline__ void cp_wait() {
    asm volatile("cp.async.wait_group %0;" :: "n"(N) : "memory");
}
__device__ __forceinline__ void mma_f16(float* c, const uint32_t* a, const uint32_t* b) {
    asm volatile(
        "mma.sync.aligned.m16n8k16.row.col.f32.f16.f16.f32 "
        "{%0,%1,%2,%3}, {%4,%5,%6,%7}, {%8,%9}, {%0,%1,%2,%3};"
        : "+f"(c[0]), "+f"(c[1]), "+f"(c[2]), "+f"(c[3])
        : "r"(a[0]), "r"(a[1]), "r"(a[2]), "r"(a[3]), "r"(b[0]), "r"(b[1]));
}
__device__ __forceinline__ void ldsm_x4(
    uint32_t& r0, uint32_t& r1, uint32_t& r2, uint32_t& r3, uint32_t addr) {
    asm volatile("ldmatrix.sync.aligned.m8n8.x4.shared.b16 {%0,%1,%2,%3}, [%4];"
        : "=r"(r0), "=r"(r1), "=r"(r2), "=r"(r3) : "r"(addr));
}
__device__ __forceinline__ void ldsm_x4_trans(
    uint32_t& r0, uint32_t& r1, uint32_t& r2, uint32_t& r3, uint32_t addr) {
    asm volatile("ldmatrix.sync.aligned.m8n8.x4.trans.shared.b16 {%0,%1,%2,%3}, [%4];"
        : "=r"(r0), "=r"(r1), "=r"(r2), "=r"(r3) : "r"(addr));
}
__device__ __forceinline__ uint32_t packh2(float a, float b) {
    __half2 h = __floats2half2_rn(a, b);
    return *(uint32_t*)&h;
}

// ======================= fp16 mma GEMM (ldmatrix fragments) =======================
#define HSTR 72
#define HT_B (128 * HSTR * 2)
#define HSTG_B (2 * HT_B)
#define GEMM_SMEM (2 * HSTG_B)

template<bool GELU, bool RES>
__global__ __launch_bounds__(128, 2) void gemm_h(
    const __half* __restrict__ A, const __half* __restrict__ B,
    const float* __restrict__ bias, const float* __restrict__ res,
    float* __restrict__ Cf, __half* __restrict__ Ch, int M, int N, int K)
{
    extern __shared__ char smem[];
    const uint32_t sb = smem_u32(smem);
    int t = threadIdx.x;
    int wid = t >> 5, lane = t & 31;
    int wm = wid >> 1, wn = wid & 1;
    int group = lane >> 2, qd = lane & 3;
    int sub = lane >> 3, lr = lane & 7;
    int m0 = blockIdx.y * 128, n0 = blockIdx.x * 128;

    auto load_chunk = [&](int c, int buf) {
        uint32_t sa = sb + buf * HSTG_B;
        uint32_t sbB = sa + HT_B;
        const __half* Ag = A + (size_t)m0 * K + c * 64;
        const __half* Bg = B + (size_t)n0 * K + c * 64;
        #pragma unroll
        for (int j = 0; j < 8; j++) {
            int idx = t + j * 128;
            int r = idx >> 3, sg = idx & 7;
            cp_async16(sa  + r * (HSTR * 2) + sg * 16, Ag + (size_t)r * K + sg * 8);
            cp_async16(sbB + r * (HSTR * 2) + sg * 16, Bg + (size_t)r * K + sg * 8);
        }
        cp_commit();
    };

    // ldmatrix lane->row mappings (per 16x16 block)
    // A: m0=[r0-8,k0-8] m1=[r8-16,k0-8] m2=[r0-8,k8-16] m3=[r8-16,k8-16]
    const uint32_t aOff = (uint32_t)(((wm * 64 + (sub & 1) * 8 + lr) * HSTR + (sub >> 1) * 8) * 2);
    // B: m0=[n0-8,k0-8] m1=[n0-8,k8-16] m2=[n8-16,k0-8] m3=[n8-16,k8-16]
    const uint32_t bOff = (uint32_t)(((wn * 64 + (sub >> 1) * 8 + lr) * HSTR + (sub & 1) * 8) * 2);

    float acc[4][8][4] = {};
    int nch = K / 64;

    load_chunk(0, 0);
    for (int c = 0; c < nch; c++) {
        if (c + 1 < nch) { load_chunk(c + 1, (c + 1) & 1); cp_wait<1>(); }
        else             { cp_wait<0>(); }
        __syncthreads();

        uint32_t sA = sb + (c & 1) * HSTG_B;
        uint32_t sB = sA + HT_B;
        #pragma unroll
        for (int ks = 0; ks < 4; ks++) {
            uint32_t af[4][4], bf[8][2];
            #pragma unroll
            for (int mt = 0; mt < 4; mt++)
                ldsm_x4(af[mt][0], af[mt][1], af[mt][2], af[mt][3],
                        sA + aOff + mt * (16 * HSTR * 2) + ks * 32);
            #pragma unroll
            for (int np = 0; np < 4; np++)
                ldsm_x4(bf[2 * np][0], bf[2 * np][1], bf[2 * np + 1][0], bf[2 * np + 1][1],
                        sB + bOff + np * (16 * HSTR * 2) + ks * 32);
            #pragma unroll
            for (int mt = 0; mt < 4; mt++)
                #pragma unroll
                for (int nt = 0; nt < 8; nt++)
                    mma_f16(acc[mt][nt], af[mt], bf[nt]);
        }
        __syncthreads();
    }

    #pragma unroll
    for (int nt = 0; nt < 8; nt++) {
        int n = n0 + wn * 64 + nt * 8 + qd * 2;
        float2 bv = *(const float2*)(bias + n);
        #pragma unroll
        for (int mt = 0; mt < 4; mt++) {
            int m = m0 + wm * 64 + mt * 16 + group;
            float* c4 = acc[mt][nt];
            float2 v0 = make_float2(c4[0] + bv.x, c4[1] + bv.y);
            float2 v1 = make_float2(c4[2] + bv.x, c4[3] + bv.y);
            if (GELU) {
                v0.x *= normcdff(v0.x); v0.y *= normcdff(v0.y);
                v1.x *= normcdff(v1.x); v1.y *= normcdff(v1.y);
            }
            if (RES) {
                float2 r0 = *(const float2*)(res + (size_t)m * N + n);
                float2 r1 = *(const float2*)(res + (size_t)(m + 8) * N + n);
                v0.x += r0.x; v0.y += r0.y; v1.x += r1.x; v1.y += r1.y;
            }
            if (Cf) {
                *(float2*)(Cf + (size_t)m * N + n) = v0;
                *(float2*)(Cf + (size_t)(m + 8) * N + n) = v1;
            }
            if (Ch) {
                *(__half2*)(Ch + (size_t)m * N + n) = __floats2half2_rn(v0.x, v0.y);
                *(__half2*)(Ch + (size_t)(m + 8) * N + n) = __floats2half2_rn(v1.x, v1.y);
            }
        }
    }
}

// ======================= weight convert+transpose: fp32 [K,N] -> fp16 [N,K] ==========
__global__ __launch_bounds__(256) void convert_wT(
    const float* __restrict__ in, __half* __restrict__ out, int K, int N)
{
    __shared__ float tile[32][33];
    int k0 = blockIdx.y * 32, n0 = blockIdx.x * 32;
    int tx = threadIdx.x, ty = threadIdx.y;
    #pragma unroll
    for (int i = 0; i < 32; i += 8)
        tile[ty + i][tx] = in[(size_t)(k0 + ty + i) * N + n0 + tx];
    __syncthreads();
    #pragma unroll
    for (int i = 0; i < 32; i += 8)
        out[(size_t)(n0 + ty + i) * K + k0 + tx] = __float2half_rn(tile[tx][ty + i]);
}

// ======================= flash attention (fp16 mma, ldmatrix) =======================
#define FS 72
#define FT_B (64 * FS * 2)                 // 9216 B per tile
#define FA_SMEM_B (5 * FT_B)               // Q + 2K + 2V = 46080 B

__global__ __launch_bounds__(128, 2) void flash_h(
    const __half* __restrict__ qkv, __half* __restrict__ O)
{
    extern __shared__ char sm[];
    const uint32_t sb = smem_u32(sm);
    const uint32_t qB = sb;
    const uint32_t kB[2] = { sb + FT_B, sb + 2 * FT_B };
    const uint32_t vB[2] = { sb + 3 * FT_B, sb + 4 * FT_B };

    int qt = blockIdx.x, bh = blockIdx.y;
    int b = bh >> 4, h = bh & 15;
    int q0 = qt * 64;
    int t = threadIdx.x, w = t >> 5, lane = t & 31, gp = lane >> 2, qd = lane & 3;
    int sub = lane >> 3, lr = lane & 7;

    // stage Q
    {
        const __half* qg = qkv + (size_t)(b * T + q0) * (3 * D) + h * HD;
        #pragma unroll
        for (int i = 0; i < 4; i++) {
            int idx = t + i * 128;
            int row = idx >> 3, sg = idx & 7;
            cp_async16(qB + row * (FS * 2) + sg * 16, qg + (size_t)row * (3 * D) + sg * 8);
        }
        cp_commit();
    }

    auto load_kv = [&](int kt, int bf) {
        const __half* kg = qkv + (size_t)(b * T + kt * 64) * (3 * D) + D + h * HD;
        #pragma unroll
        for (int i = 0; i < 4; i++) {
            int idx = t + i * 128;
            int row = idx >> 3, sg = idx & 7;
            const __half* kr = kg + (size_t)row * (3 * D) + sg * 8;
            cp_async16(kB[bf] + row * (FS * 2) + sg * 16, kr);
            cp_async16(vB[bf] + row * (FS * 2) + sg * 16, kr + D);
        }
        cp_commit();
    };

    load_kv(0, 0);
    cp_wait<1>();
    __syncthreads();

    // Q fragments via ldmatrix (A layout)
    const uint32_t aOff = (uint32_t)(((w * 16 + (sub & 1) * 8 + lr) * FS + (sub >> 1) * 8) * 2);
    uint32_t qf[4][4];
    #pragma unroll
    for (int ks = 0; ks < 4; ks++)
        ldsm_x4(qf[ks][0], qf[ks][1], qf[ks][2], qf[ks][3], qB + aOff + ks * 32);

    // K fragment base (B layout)
    const uint32_t kOff = (uint32_t)((((sub >> 1) * 8 + lr) * FS + (sub & 1) * 8) * 2);

    float m0 = -INFINITY, m1 = -INFINITY, l0 = 0.f, l1 = 0.f;
    float o[8][4] = {};

    for (int kt = 0; kt <= qt; kt++) {
        int bf = kt & 1;
        if (kt < qt) { load_kv(kt + 1, bf ^ 1); cp_wait<1>(); }
        else         { cp_wait<0>(); }
        __syncthreads();

        // S = Q @ K^T
        float s[8][4] = {};
        #pragma unroll
        for (int ks = 0; ks < 4; ks++) {
            uint32_t bfr[8][2];
            #pragma unroll
            for (int np = 0; np < 4; np++)
                ldsm_x4(bfr[2 * np][0], bfr[2 * np][1], bfr[2 * np + 1][0], bfr[2 * np + 1][1],
                        kB[bf] + kOff + np * (16 * FS * 2) + ks * 32);
            #pragma unroll
            for (int nt = 0; nt < 8; nt++)
                mma_f16(s[nt], qf[ks], bfr[nt]);
        }
        // scale + causal mask
        bool diag = (kt == qt);
        int r0l = w * 16 + gp;
        #pragma unroll
        for (int nt = 0; nt < 8; nt++) {
            int c = nt * 8 + 2 * qd;
            s[nt][0] *= 0.125f; s[nt][1] *= 0.125f;
            s[nt][2] *= 0.125f; s[nt][3] *= 0.125f;
            if (diag) {
                if (c     > r0l)     s[nt][0] = -INFINITY;
                if (c + 1 > r0l)     s[nt][1] = -INFINITY;
                if (c     > r0l + 8) s[nt][2] = -INFINITY;
                if (c + 1 > r0l + 8) s[nt][3] = -INFINITY;
            }
        }
        // online softmax
        float mx0 = -INFINITY, mx1 = -INFINITY;
        #pragma unroll
        for (int nt = 0; nt < 8; nt++) {
            mx0 = fmaxf(mx0, fmaxf(s[nt][0], s[nt][1]));
            mx1 = fmaxf(mx1, fmaxf(s[nt][2], s[nt][3]));
        }
        mx0 = fmaxf(mx0, __shfl_xor_sync(~0u, mx0, 1));
        mx0 = fmaxf(mx0, __shfl_xor_sync(~0u, mx0, 2));
        mx1 = fmaxf(mx1, __shfl_xor_sync(~0u, mx1, 1));
        mx1 = fmaxf(mx1, __shfl_xor_sync(~0u, mx1, 2));
        float mn0 = fmaxf(m0, mx0), mn1 = fmaxf(m1, mx1);
        float sc0 = __expf(m0 - mn0), sc1 = __expf(m1 - mn1);
        m0 = mn0; m1 = mn1;
        uint32_t pa[8], pb[8];
        float ls0 = 0.f, ls1 = 0.f;
        #pragma unroll
        for (int nt = 0; nt < 8; nt++) {
            float p0 = __expf(s[nt][0] - mn0), p1 = __expf(s[nt][1] - mn0);
            float p2 = __expf(s[nt][2] - mn1), p3 = __expf(s[nt][3] - mn1);
            ls0 += p0 + p1; ls1 += p2 + p3;
            pa[nt] = packh2(p0, p1);
            pb[nt] = packh2(p2, p3);
        }
        ls0 += __shfl_xor_sync(~0u, ls0, 1); ls0 += __shfl_xor_sync(~0u, ls0, 2);
        ls1 += __shfl_xor_sync(~0u, ls1, 1); ls1 += __shfl_xor_sync(~0u, ls1, 2);
        l0 = l0 * sc0 + ls0; l1 = l1 * sc1 + ls1;
        #pragma unroll
        for (int nt = 0; nt < 8; nt++) {
            o[nt][0] *= sc0; o[nt][1] *= sc0; o[nt][2] *= sc1; o[nt][3] *= sc1;
        }
        // O += P @ V
        #pragma unroll
        for (int ks = 0; ks < 4; ks++) {
            uint32_t af[4] = { pa[2 * ks], pb[2 * ks], pa[2 * ks + 1], pb[2 * ks + 1] };
            #pragma unroll
            for (int np = 0; np < 4; np++) {
                int vrow = ks * 16 + (sub & 1) * 8 + lr;
                int vcol = np * 16 + (sub >> 1) * 8;
                uint32_t addr = vB[bf] + (vrow * FS + vcol) * 2;
                uint32_t b0, b1, b2, b3;
                ldsm_x4_trans(b0, b1, b2, b3, addr);
                uint32_t bf0[2] = { b0, b1 }, bf1[2] = { b2, b3 };
                mma_f16(o[2 * np], af, bf0);
                mma_f16(o[2 * np + 1], af, bf1);
            }
        }
        __syncthreads();
    }

    float inv0 = 1.f / l0, inv1 = 1.f / l1;
    int r0 = q0 + w * 16 + gp;
    __half* O0 = O + (size_t)(b * T + r0) * D + h * HD;
    __half* O1 = O0 + (size_t)8 * D;
    #pragma unroll
    for (int nt = 0; nt < 8; nt++) {
        int c = nt * 8 + 2 * qd;
        *(__half2*)(O0 + c) = __floats2half2_rn(o[nt][0] * inv0, o[nt][1] * inv0);
        *(__half2*)(O1 + c) = __floats2half2_rn(o[nt][2] * inv1, o[nt][3] * inv1);
    }
}

// ======================= LayerNorm (fp32 in, fp16 out) =======================
__device__ __forceinline__ float block_sum256(float v, float* red) {
    int t = threadIdx.x;
    #pragma unroll
    for (int o = 16; o > 0; o >>= 1) v += __shfl_xor_sync(0xffffffffu, v, o);
    if ((t & 31) == 0) red[t >> 5] = v;
    __syncthreads();
    if (t < 32) {
        float s = (t < 8) ? red[t] : 0.0f;
        #pragma unroll
        for (int o = 4; o > 0; o >>= 1) s += __shfl_xor_sync(0xffffffffu, s, o);
        if (t == 0) red[0] = s;
    }
    __syncthreads();
    float r = red[0];
    __syncthreads();
    return r;
}

__global__ __launch_bounds__(256) void ln_kernel(
    const float* __restrict__ x, const float* __restrict__ g,
    const float* __restrict__ b, __half* __restrict__ out)
{
    __shared__ float red[32];
    int r = blockIdx.x, t = threadIdx.x;
    const float* xr = x + (size_t)r * D;
    float4 v = *(const float4*)(xr + t * 4);
    float mu = block_sum256(v.x + v.y + v.z + v.w, red) * (1.0f / D);
    float dx = v.x - mu, dy = v.y - mu, dz = v.z - mu, dw = v.w - mu;
    float var = block_sum256(dx * dx + dy * dy + dz * dz + dw * dw, red) * (1.0f / D);
    float inv = rsqrtf(var + 1e-5f);
    float4 gv = *(const float4*)(g + t * 4);
    float4 bv = *(const float4*)(b + t * 4);
    __half2 o01 = __floats2half2_rn(dx * inv * gv.x + bv.x, dy * inv * gv.y + bv.y);
    __half2 o23 = __floats2half2_rn(dz * inv * gv.z + bv.z, dw * inv * gv.w + bv.w);
    uint2 pk = make_uint2(*(uint32_t*)&o01, *(uint32_t*)&o23);
    *(uint2*)(out + (size_t)r * D + t * 4) = pk;
}

// ======================= launch =======================
template<typename Tp>
static Tp* sym_addr(const void* sym) {
    void* p = nullptr;
    cudaGetSymbolAddress(&p, sym);
    return (Tp*)p;
}

extern "C" void kernel_launch(void* const* d_in, const int* in_sizes, int n_in,
                              void* d_out, int out_size)
{
    const float* x     = (const float*)d_in[0];
    const float* w_qkv = (const float*)d_in[1];
    const float* b_qkv = (const float*)d_in[2];
    const float* w_fc  = (const float*)d_in[3];
    const float* b_fc  = (const float*)d_in[4];
    const float* ln1_g = (const float*)d_in[5];
    const float* ln1_b = (const float*)d_in[6];
    const float* ln2_g = (const float*)d_in[7];
    const float* ln2_b = (const float*)d_in[8];
    const float* w1    = (const float*)d_in[9];
    const float* b1    = (const float*)d_in[10];
    const float* w2    = (const float*)d_in[11];
    const float* b2    = (const float*)d_in[12];
    float* out = (float*)d_out;

    __half* p_h16  = sym_addr<__half>(g_h16);
    __half* p_qkv  = sym_addr<__half>(g_qkv16);
    __half* p_attn = sym_addr<__half>(g_attn16);
    float*  p_x1   = sym_addr<float>(g_x1);
    __half* p_h216 = sym_addr<__half>(g_h216);
    __half* p_ffn  = sym_addr<__half>(g_ffn16);
    __half* p_wqkv = sym_addr<__half>(g_wqkv16);
    __half* p_wfc  = sym_addr<__half>(g_wfc16);
    __half* p_w1   = sym_addr<__half>(g_w116);
    __half* p_w2   = sym_addr<__half>(g_w216);

    cudaFuncSetAttribute(gemm_h<false, false>, cudaFuncAttributeMaxDynamicSharedMemorySize, GEMM_SMEM);
    cudaFuncSetAttribute(gemm_h<false, true>,  cudaFuncAttributeMaxDynamicSharedMemorySize, GEMM_SMEM);
    cudaFuncSetAttribute(gemm_h<true,  false>, cudaFuncAttributeMaxDynamicSharedMemorySize, GEMM_SMEM);
    cudaFuncSetAttribute(flash_h, cudaFuncAttributeMaxDynamicSharedMemorySize, FA_SMEM_B);

    // weight convert+transpose: fp32 [K,N] -> fp16 [N,K]
    convert_wT<<<dim3(3 * D / 32, D / 32), dim3(32, 8)>>>(w_qkv, p_wqkv, D, 3 * D);
    convert_wT<<<dim3(D / 32, D / 32),     dim3(32, 8)>>>(w_fc,  p_wfc,  D, D);
    convert_wT<<<dim3(4 * D / 32, D / 32), dim3(32, 8)>>>(w1,    p_w1,   D, 4 * D);
    convert_wT<<<dim3(D / 32, 4 * D / 32), dim3(32, 8)>>>(w2,    p_w2,   4 * D, D);

    // 1. h = LN1(x)  (fp16)
    ln_kernel<<<ROWS, 256>>>(x, ln1_g, ln1_b, p_h16);
    // 2. qkv = h @ w_qkv + b_qkv  (fp16 out)
    gemm_h<false, false><<<dim3(3 * D / 128, ROWS / 128), 128, GEMM_SMEM>>>(
        p_h16, p_wqkv, b_qkv, nullptr, nullptr, p_qkv, ROWS, 3 * D, D);
    // 3. fused attention (fp16 in/out)
    flash_h<<<dim3(T / 64, BHCNT), 128, FA_SMEM_B>>>(p_qkv, p_attn);
    // 4. x1 = x + attn @ w_fc + b_fc  (fp32)
    gemm_h<false, true><<<dim3(D / 128, ROWS / 128), 128, GEMM_SMEM>>>(
        p_attn, p_wfc, b_fc, x, p_x1, nullptr, ROWS, D, D);
    // 5. h2 = LN2(x1)  (fp16)
    ln_kernel<<<ROWS, 256>>>(p_x1, ln2_g, ln2_b, p_h216);
    // 6. ffn = gelu(h2 @ w1 + b1)  (fp16)
    gemm_h<true, false><<<dim3(4 * D / 128, ROWS / 128), 128, GEMM_SMEM>>>(
        p_h216, p_w1, b1, nullptr, nullptr, p_ffn, ROWS, 4 * D, D);
    // 7. out = x1 + ffn @ w2 + b2  (fp32)
    gemm_h<false, true><<<dim3(D / 128, ROWS / 128), 128, GEMM_SMEM>>>(
        p_ffn, p_w2, b2, p_x1, out, nullptr, ROWS, D, 4 * D);
}